// round 13
// baseline (speedup 1.0000x reference)
#include <cuda_runtime.h>
#include <cuda_fp16.h>
#include <cstdint>

// Problem constants
#define Hh   16
#define Ss   1024
#define Dd   1024
#define HDd  64
#define Bb   8
#define BHh  (Bb*Hh)      // 128
#define Mtot (Bb*Ss)      // 8192

// scratch (device globals; no allocation allowed)
__device__ __half  g_X16[(size_t)Mtot*Dd];
__device__ __half  g_W16[(size_t)3*Dd*Dd];
__device__ uint8_t g_M8[(size_t)Bb*Ss*Ss];          // u8 mask (0/1 exact, half the L2 traffic)
__device__ __half  g_Q16[(size_t)BHh*Ss*HDd];       // head-major, pre-scaled by log2e/8
__device__ __half  g_K16[(size_t)BHh*Ss*HDd];
__device__ __half  g_V16[(size_t)BHh*Ss*HDd];

// ---------------------------------------------------------------------------
__device__ __forceinline__ uint32_t h2u(__half2 h) {
    union { __half2 h; uint32_t u; } c; c.h = h; return c.u;
}
__device__ __forceinline__ float ex2f(float x) {
    float y; asm("ex2.approx.f32 %0, %1;" : "=f"(y) : "f"(x)); return y;
}
__device__ __forceinline__ uint32_t smem_u32(const void* p) {
    uint32_t a;
    asm("{ .reg .u64 t; cvta.to.shared.u64 t, %1; cvt.u32.u64 %0, t; }" : "=r"(a) : "l"(p));
    return a;
}
#define CP_ASYNC(dst, src) \
    asm volatile("cp.async.ca.shared.global [%0], [%1], 16;" :: "r"(dst), "l"(src) : "memory")
#define CP_COMMIT() asm volatile("cp.async.commit_group;" ::: "memory")
#define CP_WAIT(n)  asm volatile("cp.async.wait_group %0;" :: "n"(n) : "memory")

__device__ __forceinline__ void ldsm_x4(uint32_t* r, uint32_t addr) {
    asm volatile("ldmatrix.sync.aligned.m8n8.x4.shared.b16 {%0,%1,%2,%3}, [%4];"
                 : "=r"(r[0]), "=r"(r[1]), "=r"(r[2]), "=r"(r[3]) : "r"(addr));
}
__device__ __forceinline__ void ldsm_x4_t(uint32_t* r, uint32_t addr) {
    asm volatile("ldmatrix.sync.aligned.m8n8.x4.trans.shared.b16 {%0,%1,%2,%3}, [%4];"
                 : "=r"(r[0]), "=r"(r[1]), "=r"(r[2]), "=r"(r[3]) : "r"(addr));
}
// fp16 m16n8k16 mma, fp32 accum in-place
__device__ __forceinline__ void mma16(float* c, const uint32_t* a, uint32_t b0, uint32_t b1) {
    asm volatile(
        "mma.sync.aligned.m16n8k16.row.col.f32.f16.f16.f32 "
        "{%0,%1,%2,%3}, {%4,%5,%6,%7}, {%8,%9}, {%0,%1,%2,%3};"
        : "+f"(c[0]), "+f"(c[1]), "+f"(c[2]), "+f"(c[3])
        : "r"(a[0]), "r"(a[1]), "r"(a[2]), "r"(a[3]), "r"(b0), "r"(b1));
}
__device__ __forceinline__ uint32_t ldsm_addr(uint32_t base, int r0, int c0b,
                                              int rowb, int lane) {
    return base + (uint32_t)(r0 + (lane & 15)) * rowb + c0b + ((lane >> 4) << 4);
}

// ---------------------------------------------------------------------------
// Merged fp32 -> {fp16, u8} convert pre-pass: one launch, 5 jobs via grid.z
//   z=0: x -> g_X16, z=1..3: W -> g_W16, z=4: mask -> g_M8 (u8 0/1)
// ---------------------------------------------------------------------------
#define N4_X (Mtot*Dd/4)       // 2097152
#define N4_W (Dd*Dd/4)         // 262144
#define N4_M (Bb*Ss*Ss/4)      // 2097152

__global__ void conv_all(const float4* __restrict__ x,
                         const float4* __restrict__ wq,
                         const float4* __restrict__ wk,
                         const float4* __restrict__ wv,
                         const float4* __restrict__ mask)
{
    const int z = blockIdx.z;
    const int i = blockIdx.x * blockDim.x + threadIdx.x;
    if (z == 0) {
        if (i < N4_X) {
            float4 v = x[i];
            __half2* d = (__half2*)g_X16;
            d[2*i]   = __floats2half2_rn(v.x, v.y);
            d[2*i+1] = __floats2half2_rn(v.z, v.w);
        }
    } else if (z <= 3) {
        if (i < N4_W) {
            const float4* s = (z == 1) ? wq : (z == 2 ? wk : wv);
            float4 v = s[i];
            __half2* d = (__half2*)(g_W16 + (size_t)(z - 1) * Dd * Dd);
            d[2*i]   = __floats2half2_rn(v.x, v.y);
            d[2*i+1] = __floats2half2_rn(v.z, v.w);
        }
    } else {
        if (i < N4_M) {
            float4 v = mask[i];
            uchar4 u;
            u.x = (v.x != 0.f); u.y = (v.y != 0.f);
            u.z = (v.z != 0.f); u.w = (v.w != 0.f);
            ((uchar4*)g_M8)[i] = u;
        }
    }
}

// ---------------------------------------------------------------------------
// Projection GEMM, fp16 HMMA (unchanged from R12 — at the HMMA issue wall):
// 256 thr, 8 warps, m32n64/warp, tile 128x128, K-step 64, 3-stage cp.async,
// single barrier per K-step. Q output pre-scaled by log2(e)/8.
// ---------------------------------------------------------------------------
#define PA_ROWB 144
#define PB_ROWB 272
#define PA_STAGE 18432
#define PB_STAGE 17408
#define NSTG 3
#define PROJ_SMEM (NSTG*(PA_STAGE + PB_STAGE))   // 107520

__global__ __launch_bounds__(256, 1) void proj16_kernel()
{
    extern __shared__ char sm[];
    const uint32_t sb = smem_u32(sm);
    const uint32_t Ab = sb, Bb_ = sb + NSTG*PA_STAGE;

    const int tid = threadIdx.x, wid = tid >> 5, lane = tid & 31;
    const int g = lane >> 2, tig = lane & 3;
    const int wm = wid & 3, wn = wid >> 2;

    const int z  = blockIdx.z;
    const int n0 = blockIdx.x * 128;
    const int m0 = blockIdx.y * 128;
    const __half* Xp = g_X16 + (size_t)m0 * Dd;
    const __half* Wp = g_W16 + (size_t)z * Dd * Dd + n0;
    __half* Out = (z == 0) ? g_Q16 : (z == 1 ? g_K16 : g_V16);
    const float osc = (z == 0) ? 0.18033688f : 1.0f;   // log2(e)/8 folded into Q

    float C[2][8][4];
    #pragma unroll
    for (int mf = 0; mf < 2; mf++)
        #pragma unroll
        for (int nf = 0; nf < 8; nf++)
            #pragma unroll
            for (int r = 0; r < 4; r++) C[mf][nf][r] = 0.f;

    auto stage = [&](int kt, int buf) {
        const int k0 = kt * 64;
        #pragma unroll
        for (int i = 0; i < 4; i++) {
            int ci = tid + 256 * i;
            int row = ci >> 3, seg = ci & 7;
            CP_ASYNC(Ab + buf * PA_STAGE + row * PA_ROWB + seg * 16,
                     Xp + (size_t)row * Dd + k0 + seg * 8);
        }
        #pragma unroll
        for (int i = 0; i < 4; i++) {
            int ci = tid + 256 * i;
            int row = ci >> 4, seg = ci & 15;
            CP_ASYNC(Bb_ + buf * PB_STAGE + row * PB_ROWB + seg * 16,
                     Wp + (size_t)(k0 + row) * Dd + seg * 8);
        }
        CP_COMMIT();
    };

    stage(0, 0);
    stage(1, 1);
    for (int kt = 0; kt < 16; kt++) {
        if (kt == 15) { CP_WAIT(0); }
        else          { CP_WAIT(1); }
        __syncthreads();   // all warps done with iter kt-1 (buf (kt-1)%3)
        if (kt + 2 < 16) stage(kt + 2, (kt + 2) % NSTG);

        const int buf = kt % NSTG;
        const uint32_t ab = Ab + buf * PA_STAGE;
        const uint32_t bbuf = Bb_ + buf * PB_STAGE;

        uint32_t a[2][4], an[2][4], r[4], rn[4];
        ldsm_x4(a[0], ldsm_addr(ab, wm * 32,      0, PA_ROWB, lane));
        ldsm_x4(a[1], ldsm_addr(ab, wm * 32 + 16, 0, PA_ROWB, lane));
        ldsm_x4_t(r, ldsm_addr(bbuf, 0, (wn * 64) * 2, PB_ROWB, lane));

        #pragma unroll
        for (int k16 = 0; k16 < 4; k16++) {
            #pragma unroll
            for (int nfp = 0; nfp < 4; nfp++) {
                if (nfp < 3) {
                    ldsm_x4_t(rn, ldsm_addr(bbuf, k16 * 16,
                                            (wn * 64 + (nfp + 1) * 16) * 2, PB_ROWB, lane));
                } else if (k16 < 3) {
                    ldsm_x4_t(rn, ldsm_addr(bbuf, (k16 + 1) * 16,
                                            (wn * 64) * 2, PB_ROWB, lane));
                    ldsm_x4(an[0], ldsm_addr(ab, wm * 32,      (k16 + 1) * 32, PA_ROWB, lane));
                    ldsm_x4(an[1], ldsm_addr(ab, wm * 32 + 16, (k16 + 1) * 32, PA_ROWB, lane));
                }
                mma16(C[0][2*nfp],     a[0], r[0], r[1]);
                mma16(C[0][2*nfp + 1], a[0], r[2], r[3]);
                mma16(C[1][2*nfp],     a[1], r[0], r[1]);
                mma16(C[1][2*nfp + 1], a[1], r[2], r[3]);
                #pragma unroll
                for (int q = 0; q < 4; q++) r[q] = rn[q];
            }
            #pragma unroll
            for (int q = 0; q < 4; q++) { a[0][q] = an[0][q]; a[1][q] = an[1][q]; }
        }
    }

    // epilogue: head-major fp16 scatter
    const int h = (n0 >> 6) + wn;
    #pragma unroll
    for (int mf = 0; mf < 2; mf++) {
        int m = m0 + wm * 32 + mf * 16 + g;
        int bidx = m >> 10, s = m & 1023;
        __half* base  = Out + ((size_t)(bidx * Hh + h) * Ss + s) * HDd;
        __half* base2 = base + 8 * HDd;
        #pragma unroll
        for (int nf = 0; nf < 8; nf++) {
            int d = nf * 8 + 2 * tig;
            *(__half2*)(base + d)  = __floats2half2_rn(C[mf][nf][0]*osc, C[mf][nf][1]*osc);
            *(__half2*)(base2 + d) = __floats2half2_rn(C[mf][nf][2]*osc, C[mf][nf][3]*osc);
        }
    }
}

// ---------------------------------------------------------------------------
// Attention, fp16 HMMA, occ 2: CTA = 128 q-rows, 8 warps m16 each.
// 128-row double-buffered KV stages. u8 mask (half the L2 traffic; SEL not MUL).
// ---------------------------------------------------------------------------
#define A_ROWB 144                  // 72 halves
#define AQ_BYTES (128*A_ROWB)       // 18432
#define AKV_BYTES (128*A_ROWB)      // 18432 per 128-row stage
#define ATTN_SMEM (AQ_BYTES + 4*AKV_BYTES)   // 92160 (K x2, V x2)

__global__ __launch_bounds__(256, 2) void attn16_kernel(float* __restrict__ out)
{
    extern __shared__ char sm[];
    const uint32_t sb = smem_u32(sm);
    const uint32_t Qb = sb, Kb = sb + AQ_BYTES, Vb = Kb + 2*AKV_BYTES;

    const int tid = threadIdx.x, w = tid >> 5, lane = tid & 31;
    const int g = lane >> 2, tig = lane & 3;
    const int bh = blockIdx.y, b = bh >> 4, h = bh & 15;
    const int q0 = blockIdx.x * 128;
    const int i0 = w * 16;

    const __half* Qg = g_Q16 + (size_t)bh * Ss * HDd + (size_t)q0 * HDd;
    const __half* Kg = g_K16 + (size_t)bh * Ss * HDd;
    const __half* Vg = g_V16 + (size_t)bh * Ss * HDd;
    const uint8_t* mbase = g_M8 + ((size_t)b * Ss + q0 + i0) * Ss;

    auto stageKV = [&](int t0, int buf) {
        #pragma unroll
        for (int i = 0; i < 4; i++) {          // K: 1024 chunks / 256 thr
            int ci = tid + 256 * i;
            int row = ci >> 3, seg = ci & 7;
            CP_ASYNC(Kb + buf * AKV_BYTES + row * A_ROWB + seg * 16,
                     Kg + (size_t)(t0 + row) * HDd + seg * 8);
        }
        #pragma unroll
        for (int i = 0; i < 4; i++) {          // V
            int ci = tid + 256 * i;
            int row = ci >> 3, seg = ci & 7;
            CP_ASYNC(Vb + buf * AKV_BYTES + row * A_ROWB + seg * 16,
                     Vg + (size_t)(t0 + row) * HDd + seg * 8);
        }
        CP_COMMIT();
    };

    // prologue: Q (1024 chunks) + KV stage 0 -> one group
    #pragma unroll
    for (int i = 0; i < 4; i++) {
        int ci = tid + 256 * i;
        int row = ci >> 3, seg = ci & 7;
        CP_ASYNC(Qb + row * A_ROWB + seg * 16, Qg + (size_t)row * HDd + seg * 8);
    }
    stageKV(0, 0);
    CP_WAIT(0);
    __syncthreads();

    uint32_t qf[4][4];
    #pragma unroll
    for (int k16 = 0; k16 < 4; k16++)
        ldsm_x4(qf[k16], ldsm_addr(Qb, i0, k16 * 32, A_ROWB, lane));

    float O[8][4];
    #pragma unroll
    for (int nf = 0; nf < 8; nf++)
        #pragma unroll
        for (int r = 0; r < 4; r++) O[nf][r] = 0.f;
    float rs0 = 0.f, rs1 = 0.f;

    for (int tt = 0; tt < 8; tt++) {
        const int buf = tt & 1;
        if (tt < 7) { stageKV((tt + 1) * 128, buf ^ 1); CP_WAIT(1); }
        else        { CP_WAIT(0); }
        __syncthreads();

        const uint32_t kb = Kb + buf * AKV_BYTES;
        const uint32_t vb = Vb + buf * AKV_BYTES;

        #pragma unroll
        for (int half = 0; half < 2; half++) {
            const int t0 = tt * 128 + half * 64;
            const int r0 = half * 64;

            // S = Q K^T (log2 units; Q prescaled)
            float S[8][4];
            #pragma unroll
            for (int nf = 0; nf < 8; nf++)
                #pragma unroll
                for (int r = 0; r < 4; r++) S[nf][r] = 0.f;
            #pragma unroll
            for (int k16 = 0; k16 < 4; k16++) {
                #pragma unroll
                for (int nfp = 0; nfp < 4; nfp++) {
                    uint32_t r[4];
                    ldsm_x4(r, ldsm_addr(kb, r0 + nfp * 16, k16 * 32, A_ROWB, lane));
                    mma16(S[2*nfp],     qf[k16], r[0], r[2]);
                    mma16(S[2*nfp + 1], qf[k16], r[1], r[3]);
                }
            }

            // P = mask ? ex2(S) : 0 (u8 mask), packed fp16; rowsum fp32
            uint32_t Pp[8][2];
            #pragma unroll
            for (int nf = 0; nf < 8; nf++) {
                const uint8_t* mp = mbase + (size_t)g * Ss + t0 + nf * 8 + 2 * tig;
                uchar2 m01 = *(const uchar2*)mp;
                uchar2 m23 = *(const uchar2*)(mp + 8 * Ss);
                float e0 = m01.x ? ex2f(S[nf][0]) : 0.f;
                float e1 = m01.y ? ex2f(S[nf][1]) : 0.f;
                float e2 = m23.x ? ex2f(S[nf][2]) : 0.f;
                float e3 = m23.y ? ex2f(S[nf][3]) : 0.f;
                rs0 += e0 + e1;
                rs1 += e2 + e3;
                Pp[nf][0] = h2u(__floats2half2_rn(e0, e1));
                Pp[nf][1] = h2u(__floats2half2_rn(e2, e3));
            }

            // O += P V
            #pragma unroll
            for (int kt = 0; kt < 4; kt++) {
                #pragma unroll
                for (int nfp = 0; nfp < 4; nfp++) {
                    uint32_t r[4];
                    ldsm_x4_t(r, ldsm_addr(vb, r0 + kt * 16, nfp * 32, A_ROWB, lane));
                    uint32_t a[4] = { Pp[2*kt][0], Pp[2*kt][1],
                                      Pp[2*kt + 1][0], Pp[2*kt + 1][1] };
                    mma16(O[2*nfp],     a, r[0], r[1]);
                    mma16(O[2*nfp + 1], a, r[2], r[3]);
                }
            }
        }
        __syncthreads();
    }

    // normalize + store
    rs0 += __shfl_xor_sync(0xffffffffu, rs0, 1);
    rs0 += __shfl_xor_sync(0xffffffffu, rs0, 2);
    rs1 += __shfl_xor_sync(0xffffffffu, rs1, 1);
    rs1 += __shfl_xor_sync(0xffffffffu, rs1, 2);
    const float inv0 = 1.0f / (rs0 + 1e-8f);
    const float inv1 = 1.0f / (rs1 + 1e-8f);
    float* o0 = out + ((size_t)b * Ss + q0 + i0 + g) * Dd + h * HDd;
    float* o1 = o0 + 8 * Dd;
    #pragma unroll
    for (int nf = 0; nf < 8; nf++) {
        int d = nf * 8 + 2 * tig;
        *(float2*)(o0 + d) = make_float2(O[nf][0] * inv0, O[nf][1] * inv0);
        *(float2*)(o1 + d) = make_float2(O[nf][2] * inv1, O[nf][3] * inv1);
    }
}

// ---------------------------------------------------------------------------
extern "C" void kernel_launch(void* const* d_in, const int* in_sizes, int n_in,
                              void* d_out, int out_size)
{
    const float* x    = (const float*)d_in[0];
    const float* mask = (const float*)d_in[1];
    const float* Wq   = (const float*)d_in[2];
    const float* Wk   = (const float*)d_in[3];
    const float* Wv   = (const float*)d_in[4];
    float* out = (float*)d_out;

    // 1) merged convert pre-pass (x, 3 weights, mask) in ONE launch
    {
        dim3 cgrid((N4_X + 255) / 256, 1, 5);
        conv_all<<<cgrid, 256>>>((const float4*)x, (const float4*)Wq,
                                 (const float4*)Wk, (const float4*)Wv,
                                 (const float4*)mask);
    }

    // 2) projections (fp16 HMMA, at the mma.sync issue wall)
    cudaFuncSetAttribute(proj16_kernel, cudaFuncAttributeMaxDynamicSharedMemorySize,
                         PROJ_SMEM);
    dim3 pgrid(Dd / 128, Mtot / 128, 3);
    proj16_kernel<<<pgrid, 256, PROJ_SMEM>>>();

    // 3) attention (fp16 HMMA, occ 2, 128-row KV stages, u8 mask)
    cudaFuncSetAttribute(attn16_kernel, cudaFuncAttributeMaxDynamicSharedMemorySize,
                         ATTN_SMEM);
    dim3 agrid(Ss / 128, BHh);              // (8, 128)
    attn16_kernel<<<agrid, 256, ATTN_SMEM>>>(out);
}

// round 14
// speedup vs baseline: 1.0677x; 1.0677x over previous
#include <cuda_runtime.h>
#include <cuda_fp16.h>
#include <cstdint>

// Problem constants
#define Hh   16
#define Ss   1024
#define Dd   1024
#define HDd  64
#define Bb   8
#define BHh  (Bb*Hh)      // 128
#define Mtot (Bb*Ss)      // 8192

// fp16 scratch (device globals; no allocation allowed)
__device__ __half g_X16[(size_t)Mtot*Dd];
__device__ __half g_W16[(size_t)3*Dd*Dd];
__device__ __half g_M16[(size_t)Bb*Ss*Ss];         // fp16 mask (0/1 exact)
__device__ __half g_Q16[(size_t)BHh*Ss*HDd];       // head-major, pre-scaled by log2e/8
__device__ __half g_K16[(size_t)BHh*Ss*HDd];
__device__ __half g_V16[(size_t)BHh*Ss*HDd];

// ---------------------------------------------------------------------------
__device__ __forceinline__ uint32_t h2u(__half2 h) {
    union { __half2 h; uint32_t u; } c; c.h = h; return c.u;
}
__device__ __forceinline__ float ex2f(float x) {
    float y; asm("ex2.approx.f32 %0, %1;" : "=f"(y) : "f"(x)); return y;
}
__device__ __forceinline__ uint32_t smem_u32(const void* p) {
    uint32_t a;
    asm("{ .reg .u64 t; cvta.to.shared.u64 t, %1; cvt.u32.u64 %0, t; }" : "=r"(a) : "l"(p));
    return a;
}
#define CP_ASYNC(dst, src) \
    asm volatile("cp.async.ca.shared.global [%0], [%1], 16;" :: "r"(dst), "l"(src) : "memory")
#define CP_COMMIT() asm volatile("cp.async.commit_group;" ::: "memory")
#define CP_WAIT(n)  asm volatile("cp.async.wait_group %0;" :: "n"(n) : "memory")

__device__ __forceinline__ void ldsm_x4(uint32_t* r, uint32_t addr) {
    asm volatile("ldmatrix.sync.aligned.m8n8.x4.shared.b16 {%0,%1,%2,%3}, [%4];"
                 : "=r"(r[0]), "=r"(r[1]), "=r"(r[2]), "=r"(r[3]) : "r"(addr));
}
__device__ __forceinline__ void ldsm_x4_t(uint32_t* r, uint32_t addr) {
    asm volatile("ldmatrix.sync.aligned.m8n8.x4.trans.shared.b16 {%0,%1,%2,%3}, [%4];"
                 : "=r"(r[0]), "=r"(r[1]), "=r"(r[2]), "=r"(r[3]) : "r"(addr));
}
// fp16 m16n8k16 mma, fp32 accum in-place
__device__ __forceinline__ void mma16(float* c, const uint32_t* a, uint32_t b0, uint32_t b1) {
    asm volatile(
        "mma.sync.aligned.m16n8k16.row.col.f32.f16.f16.f32 "
        "{%0,%1,%2,%3}, {%4,%5,%6,%7}, {%8,%9}, {%0,%1,%2,%3};"
        : "+f"(c[0]), "+f"(c[1]), "+f"(c[2]), "+f"(c[3])
        : "r"(a[0]), "r"(a[1]), "r"(a[2]), "r"(a[3]), "r"(b0), "r"(b1));
}
__device__ __forceinline__ uint32_t ldsm_addr(uint32_t base, int r0, int c0b,
                                              int rowb, int lane) {
    return base + (uint32_t)(r0 + (lane & 15)) * rowb + c0b + ((lane >> 4) << 4);
}

// ---------------------------------------------------------------------------
// fp32 -> fp16 convert pre-passes (x and weights only; mask rides inside proj)
// ---------------------------------------------------------------------------
__global__ void conv_fp16(const float4* __restrict__ src, __half2* __restrict__ dst, int n4)
{
    int i = blockIdx.x * blockDim.x + threadIdx.x;
    if (i < n4) {
        float4 v = src[i];
        dst[2*i]   = __floats2half2_rn(v.x, v.y);
        dst[2*i+1] = __floats2half2_rn(v.z, v.w);
    }
}
__global__ void conv_w3(const float4* __restrict__ Wq, const float4* __restrict__ Wk,
                        const float4* __restrict__ Wv, int n4)
{
    int i = blockIdx.x * blockDim.x + threadIdx.x;
    const float4* src = (blockIdx.z == 0) ? Wq : (blockIdx.z == 1 ? Wk : Wv);
    __half2* dst = (__half2*)(g_W16 + (size_t)blockIdx.z * Dd * Dd);
    if (i < n4) {
        float4 v = src[i];
        dst[2*i]   = __floats2half2_rn(v.x, v.y);
        dst[2*i+1] = __floats2half2_rn(v.z, v.w);
    }
}

// ---------------------------------------------------------------------------
// Projection GEMM, fp16 HMMA (R12 compute path, at the HMMA issue wall):
// 256 thr, 8 warps, m32n64/warp, tile 128x128, K-step 64, 3-stage cp.async,
// single barrier per K-step. Q output pre-scaled by log2(e)/8.
// grid.z==3 slice: mask fp32->fp16 conversion, co-resident with proj CTAs
// (0 smem, few regs -> overlaps proj's idle memory pipes; off critical path).
// ---------------------------------------------------------------------------
#define PA_ROWB 144
#define PB_ROWB 272
#define PA_STAGE 18432
#define PB_STAGE 17408
#define NSTG 3
#define PROJ_SMEM (NSTG*(PA_STAGE + PB_STAGE))   // 107520
#define N4_M (Bb*Ss*Ss/4)                        // 2097152 float4s

__global__ __launch_bounds__(256, 1) void proj16_kernel(const float4* __restrict__ mask)
{
    // ---- grid.z == 3: mask conversion slice (512 blocks x 4096 float4) ----
    if (blockIdx.z == 3) {
        const int bid = blockIdx.y * gridDim.x + blockIdx.x;   // 0..511
        __half2* d = (__half2*)g_M16;
        const int base = bid * 4096;
        #pragma unroll
        for (int i = 0; i < 16; i++) {
            int j = base + i * 256 + threadIdx.x;
            float4 v = mask[j];
            d[2*j]   = __floats2half2_rn(v.x, v.y);
            d[2*j+1] = __floats2half2_rn(v.z, v.w);
        }
        return;
    }

    extern __shared__ char sm[];
    const uint32_t sb = smem_u32(sm);
    const uint32_t Ab = sb, Bb_ = sb + NSTG*PA_STAGE;

    const int tid = threadIdx.x, wid = tid >> 5, lane = tid & 31;
    const int g = lane >> 2, tig = lane & 3;
    const int wm = wid & 3, wn = wid >> 2;

    const int z  = blockIdx.z;
    const int n0 = blockIdx.x * 128;
    const int m0 = blockIdx.y * 128;
    const __half* Xp = g_X16 + (size_t)m0 * Dd;
    const __half* Wp = g_W16 + (size_t)z * Dd * Dd + n0;
    __half* Out = (z == 0) ? g_Q16 : (z == 1 ? g_K16 : g_V16);
    const float osc = (z == 0) ? 0.18033688f : 1.0f;   // log2(e)/8 folded into Q

    float C[2][8][4];
    #pragma unroll
    for (int mf = 0; mf < 2; mf++)
        #pragma unroll
        for (int nf = 0; nf < 8; nf++)
            #pragma unroll
            for (int r = 0; r < 4; r++) C[mf][nf][r] = 0.f;

    auto stage = [&](int kt, int buf) {
        const int k0 = kt * 64;
        #pragma unroll
        for (int i = 0; i < 4; i++) {
            int ci = tid + 256 * i;
            int row = ci >> 3, seg = ci & 7;
            CP_ASYNC(Ab + buf * PA_STAGE + row * PA_ROWB + seg * 16,
                     Xp + (size_t)row * Dd + k0 + seg * 8);
        }
        #pragma unroll
        for (int i = 0; i < 4; i++) {
            int ci = tid + 256 * i;
            int row = ci >> 4, seg = ci & 15;
            CP_ASYNC(Bb_ + buf * PB_STAGE + row * PB_ROWB + seg * 16,
                     Wp + (size_t)(k0 + row) * Dd + seg * 8);
        }
        CP_COMMIT();
    };

    stage(0, 0);
    stage(1, 1);
    for (int kt = 0; kt < 16; kt++) {
        if (kt == 15) { CP_WAIT(0); }
        else          { CP_WAIT(1); }
        __syncthreads();   // all warps done with iter kt-1 (buf (kt-1)%3)
        if (kt + 2 < 16) stage(kt + 2, (kt + 2) % NSTG);

        const int buf = kt % NSTG;
        const uint32_t ab = Ab + buf * PA_STAGE;
        const uint32_t bbuf = Bb_ + buf * PB_STAGE;

        uint32_t a[2][4], an[2][4], r[4], rn[4];
        ldsm_x4(a[0], ldsm_addr(ab, wm * 32,      0, PA_ROWB, lane));
        ldsm_x4(a[1], ldsm_addr(ab, wm * 32 + 16, 0, PA_ROWB, lane));
        ldsm_x4_t(r, ldsm_addr(bbuf, 0, (wn * 64) * 2, PB_ROWB, lane));

        #pragma unroll
        for (int k16 = 0; k16 < 4; k16++) {
            #pragma unroll
            for (int nfp = 0; nfp < 4; nfp++) {
                if (nfp < 3) {
                    ldsm_x4_t(rn, ldsm_addr(bbuf, k16 * 16,
                                            (wn * 64 + (nfp + 1) * 16) * 2, PB_ROWB, lane));
                } else if (k16 < 3) {
                    ldsm_x4_t(rn, ldsm_addr(bbuf, (k16 + 1) * 16,
                                            (wn * 64) * 2, PB_ROWB, lane));
                    ldsm_x4(an[0], ldsm_addr(ab, wm * 32,      (k16 + 1) * 32, PA_ROWB, lane));
                    ldsm_x4(an[1], ldsm_addr(ab, wm * 32 + 16, (k16 + 1) * 32, PA_ROWB, lane));
                }
                mma16(C[0][2*nfp],     a[0], r[0], r[1]);
                mma16(C[0][2*nfp + 1], a[0], r[2], r[3]);
                mma16(C[1][2*nfp],     a[1], r[0], r[1]);
                mma16(C[1][2*nfp + 1], a[1], r[2], r[3]);
                #pragma unroll
                for (int q = 0; q < 4; q++) r[q] = rn[q];
            }
            #pragma unroll
            for (int q = 0; q < 4; q++) { a[0][q] = an[0][q]; a[1][q] = an[1][q]; }
        }
    }

    // epilogue: head-major fp16 scatter
    const int h = (n0 >> 6) + wn;
    #pragma unroll
    for (int mf = 0; mf < 2; mf++) {
        int m = m0 + wm * 32 + mf * 16 + g;
        int bidx = m >> 10, s = m & 1023;
        __half* base  = Out + ((size_t)(bidx * Hh + h) * Ss + s) * HDd;
        __half* base2 = base + 8 * HDd;
        #pragma unroll
        for (int nf = 0; nf < 8; nf++) {
            int d = nf * 8 + 2 * tig;
            *(__half2*)(base + d)  = __floats2half2_rn(C[mf][nf][0]*osc, C[mf][nf][1]*osc);
            *(__half2*)(base2 + d) = __floats2half2_rn(C[mf][nf][2]*osc, C[mf][nf][3]*osc);
        }
    }
}

// ---------------------------------------------------------------------------
// Attention, fp16 HMMA, occ 2 (byte-identical to R12): CTA = 128 q-rows,
// 8 warps m16 each, 128-row double-buffered KV stages, fp16 mask.
// ---------------------------------------------------------------------------
#define A_ROWB 144                  // 72 halves
#define AQ_BYTES (128*A_ROWB)       // 18432
#define AKV_BYTES (128*A_ROWB)      // 18432 per 128-row stage
#define ATTN_SMEM (AQ_BYTES + 4*AKV_BYTES)   // 92160 (K x2, V x2)

__global__ __launch_bounds__(256, 2) void attn16_kernel(float* __restrict__ out)
{
    extern __shared__ char sm[];
    const uint32_t sb = smem_u32(sm);
    const uint32_t Qb = sb, Kb = sb + AQ_BYTES, Vb = Kb + 2*AKV_BYTES;

    const int tid = threadIdx.x, w = tid >> 5, lane = tid & 31;
    const int g = lane >> 2, tig = lane & 3;
    const int bh = blockIdx.y, b = bh >> 4, h = bh & 15;
    const int q0 = blockIdx.x * 128;
    const int i0 = w * 16;

    const __half* Qg = g_Q16 + (size_t)bh * Ss * HDd + (size_t)q0 * HDd;
    const __half* Kg = g_K16 + (size_t)bh * Ss * HDd;
    const __half* Vg = g_V16 + (size_t)bh * Ss * HDd;
    const __half* mbase = g_M16 + ((size_t)b * Ss + q0 + i0) * Ss;

    auto stageKV = [&](int t0, int buf) {
        #pragma unroll
        for (int i = 0; i < 4; i++) {          // K: 1024 chunks / 256 thr
            int ci = tid + 256 * i;
            int row = ci >> 3, seg = ci & 7;
            CP_ASYNC(Kb + buf * AKV_BYTES + row * A_ROWB + seg * 16,
                     Kg + (size_t)(t0 + row) * HDd + seg * 8);
        }
        #pragma unroll
        for (int i = 0; i < 4; i++) {          // V
            int ci = tid + 256 * i;
            int row = ci >> 3, seg = ci & 7;
            CP_ASYNC(Vb + buf * AKV_BYTES + row * A_ROWB + seg * 16,
                     Vg + (size_t)(t0 + row) * HDd + seg * 8);
        }
        CP_COMMIT();
    };

    // prologue: Q (1024 chunks) + KV stage 0 -> one group
    #pragma unroll
    for (int i = 0; i < 4; i++) {
        int ci = tid + 256 * i;
        int row = ci >> 3, seg = ci & 7;
        CP_ASYNC(Qb + row * A_ROWB + seg * 16, Qg + (size_t)row * HDd + seg * 8);
    }
    stageKV(0, 0);
    CP_WAIT(0);
    __syncthreads();

    uint32_t qf[4][4];
    #pragma unroll
    for (int k16 = 0; k16 < 4; k16++)
        ldsm_x4(qf[k16], ldsm_addr(Qb, i0, k16 * 32, A_ROWB, lane));

    float O[8][4];
    #pragma unroll
    for (int nf = 0; nf < 8; nf++)
        #pragma unroll
        for (int r = 0; r < 4; r++) O[nf][r] = 0.f;
    float rs0 = 0.f, rs1 = 0.f;

    for (int tt = 0; tt < 8; tt++) {
        const int buf = tt & 1;
        if (tt < 7) { stageKV((tt + 1) * 128, buf ^ 1); CP_WAIT(1); }
        else        { CP_WAIT(0); }
        __syncthreads();

        const uint32_t kb = Kb + buf * AKV_BYTES;
        const uint32_t vb = Vb + buf * AKV_BYTES;

        #pragma unroll
        for (int half = 0; half < 2; half++) {
            const int t0 = tt * 128 + half * 64;
            const int r0 = half * 64;

            // S = Q K^T (log2 units; Q prescaled)
            float S[8][4];
            #pragma unroll
            for (int nf = 0; nf < 8; nf++)
                #pragma unroll
                for (int r = 0; r < 4; r++) S[nf][r] = 0.f;
            #pragma unroll
            for (int k16 = 0; k16 < 4; k16++) {
                #pragma unroll
                for (int nfp = 0; nfp < 4; nfp++) {
                    uint32_t r[4];
                    ldsm_x4(r, ldsm_addr(kb, r0 + nfp * 16, k16 * 32, A_ROWB, lane));
                    mma16(S[2*nfp],     qf[k16], r[0], r[2]);
                    mma16(S[2*nfp + 1], qf[k16], r[1], r[3]);
                }
            }

            // P = ex2(S) * mask (fp16 mask loads), packed fp16; rowsum fp32
            uint32_t Pp[8][2];
            #pragma unroll
            for (int nf = 0; nf < 8; nf++) {
                const __half* mp = mbase + (size_t)g * Ss + t0 + nf * 8 + 2 * tig;
                float2 m01 = __half22float2(*(const __half2*)mp);
                float2 m23 = __half22float2(*(const __half2*)(mp + 8 * Ss));
                float e0 = ex2f(S[nf][0]) * m01.x;
                float e1 = ex2f(S[nf][1]) * m01.y;
                float e2 = ex2f(S[nf][2]) * m23.x;
                float e3 = ex2f(S[nf][3]) * m23.y;
                rs0 += e0 + e1;
                rs1 += e2 + e3;
                Pp[nf][0] = h2u(__floats2half2_rn(e0, e1));
                Pp[nf][1] = h2u(__floats2half2_rn(e2, e3));
            }

            // O += P V
            #pragma unroll
            for (int kt = 0; kt < 4; kt++) {
                #pragma unroll
                for (int nfp = 0; nfp < 4; nfp++) {
                    uint32_t r[4];
                    ldsm_x4_t(r, ldsm_addr(vb, r0 + kt * 16, nfp * 32, A_ROWB, lane));
                    uint32_t a[4] = { Pp[2*kt][0], Pp[2*kt][1],
                                      Pp[2*kt + 1][0], Pp[2*kt + 1][1] };
                    mma16(O[2*nfp],     a, r[0], r[1]);
                    mma16(O[2*nfp + 1], a, r[2], r[3]);
                }
            }
        }
        __syncthreads();
    }

    // normalize + store
    rs0 += __shfl_xor_sync(0xffffffffu, rs0, 1);
    rs0 += __shfl_xor_sync(0xffffffffu, rs0, 2);
    rs1 += __shfl_xor_sync(0xffffffffu, rs1, 1);
    rs1 += __shfl_xor_sync(0xffffffffu, rs1, 2);
    const float inv0 = 1.0f / (rs0 + 1e-8f);
    const float inv1 = 1.0f / (rs1 + 1e-8f);
    float* o0 = out + ((size_t)b * Ss + q0 + i0 + g) * Dd + h * HDd;
    float* o1 = o0 + 8 * Dd;
    #pragma unroll
    for (int nf = 0; nf < 8; nf++) {
        int d = nf * 8 + 2 * tig;
        *(float2*)(o0 + d) = make_float2(O[nf][0] * inv0, O[nf][1] * inv0);
        *(float2*)(o1 + d) = make_float2(O[nf][2] * inv1, O[nf][3] * inv1);
    }
}

// ---------------------------------------------------------------------------
extern "C" void kernel_launch(void* const* d_in, const int* in_sizes, int n_in,
                              void* d_out, int out_size)
{
    const float* x    = (const float*)d_in[0];
    const float* mask = (const float*)d_in[1];
    const float* Wq   = (const float*)d_in[2];
    const float* Wk   = (const float*)d_in[3];
    const float* Wv   = (const float*)d_in[4];
    float* out = (float*)d_out;

    __half* gX; cudaGetSymbolAddress((void**)&gX, g_X16);

    // 1) fp32 -> fp16 pre-pass (x and weights only; mask converts inside proj)
    const int n4x = Mtot * Dd / 4;
    const int n4w = Dd * Dd / 4;
    conv_fp16<<<(n4x + 255) / 256, 256>>>((const float4*)x, (__half2*)gX, n4x);
    {
        dim3 wgrid((n4w + 255) / 256, 1, 3);
        conv_w3<<<wgrid, 256>>>((const float4*)Wq, (const float4*)Wk,
                                (const float4*)Wv, n4w);
    }

    // 2) projections (fp16 HMMA) + mask conversion as co-resident grid.z=3 slice
    cudaFuncSetAttribute(proj16_kernel, cudaFuncAttributeMaxDynamicSharedMemorySize,
                         PROJ_SMEM);
    dim3 pgrid(Dd / 128, Mtot / 128, 4);   // z=0..2 proj, z=3 mask conv (512 blocks)
    proj16_kernel<<<pgrid, 256, PROJ_SMEM>>>((const float4*)mask);

    // 3) attention (fp16 HMMA, occ 2, 128-row KV stages)
    cudaFuncSetAttribute(attn16_kernel, cudaFuncAttributeMaxDynamicSharedMemorySize,
                         ATTN_SMEM);
    dim3 agrid(Ss / 128, BHh);              // (8, 128)
    attn16_kernel<<<agrid, 256, ATTN_SMEM>>>(out);
}

// round 15
// speedup vs baseline: 1.0925x; 1.0232x over previous
#include <cuda_runtime.h>
#include <cuda_fp16.h>
#include <cstdint>

// Problem constants
#define Hh   16
#define Ss   1024
#define Dd   1024
#define HDd  64
#define Bb   8
#define BHh  (Bb*Hh)      // 128
#define Mtot (Bb*Ss)      // 8192

// fp16 scratch (device globals; no allocation allowed)
__device__ __half g_X16[(size_t)Mtot*Dd];
__device__ __half g_W16[(size_t)3*Dd*Dd];
__device__ __half g_M16[(size_t)Bb*Ss*Ss];         // fp16 mask (0/1 exact)
__device__ __half g_Q16[(size_t)BHh*Ss*HDd];       // head-major, pre-scaled by log2e/8
__device__ __half g_K16[(size_t)BHh*Ss*HDd];
__device__ __half g_V16[(size_t)BHh*Ss*HDd];

// ---------------------------------------------------------------------------
__device__ __forceinline__ uint32_t h2u(__half2 h) {
    union { __half2 h; uint32_t u; } c; c.h = h; return c.u;
}
__device__ __forceinline__ float ex2f(float x) {
    float y; asm("ex2.approx.f32 %0, %1;" : "=f"(y) : "f"(x)); return y;
}
__device__ __forceinline__ uint32_t smem_u32(const void* p) {
    uint32_t a;
    asm("{ .reg .u64 t; cvta.to.shared.u64 t, %1; cvt.u32.u64 %0, t; }" : "=r"(a) : "l"(p));
    return a;
}
#define CP_ASYNC(dst, src) \
    asm volatile("cp.async.ca.shared.global [%0], [%1], 16;" :: "r"(dst), "l"(src) : "memory")
#define CP_COMMIT() asm volatile("cp.async.commit_group;" ::: "memory")
#define CP_WAIT(n)  asm volatile("cp.async.wait_group %0;" :: "n"(n) : "memory")

__device__ __forceinline__ void ldsm_x4(uint32_t* r, uint32_t addr) {
    asm volatile("ldmatrix.sync.aligned.m8n8.x4.shared.b16 {%0,%1,%2,%3}, [%4];"
                 : "=r"(r[0]), "=r"(r[1]), "=r"(r[2]), "=r"(r[3]) : "r"(addr));
}
__device__ __forceinline__ void ldsm_x4_t(uint32_t* r, uint32_t addr) {
    asm volatile("ldmatrix.sync.aligned.m8n8.x4.trans.shared.b16 {%0,%1,%2,%3}, [%4];"
                 : "=r"(r[0]), "=r"(r[1]), "=r"(r[2]), "=r"(r[3]) : "r"(addr));
}
// fp16 m16n8k16 mma, fp32 accum in-place
__device__ __forceinline__ void mma16(float* c, const uint32_t* a, uint32_t b0, uint32_t b1) {
    asm volatile(
        "mma.sync.aligned.m16n8k16.row.col.f32.f16.f16.f32 "
        "{%0,%1,%2,%3}, {%4,%5,%6,%7}, {%8,%9}, {%0,%1,%2,%3};"
        : "+f"(c[0]), "+f"(c[1]), "+f"(c[2]), "+f"(c[3])
        : "r"(a[0]), "r"(a[1]), "r"(a[2]), "r"(a[3]), "r"(b0), "r"(b1));
}
__device__ __forceinline__ uint32_t ldsm_addr(uint32_t base, int r0, int c0b,
                                              int rowb, int lane) {
    return base + (uint32_t)(r0 + (lane & 15)) * rowb + c0b + ((lane >> 4) << 4);
}

// ---------------------------------------------------------------------------
// fp32 -> fp16 convert pre-passes (x and weights only; mask rides inside proj)
// ---------------------------------------------------------------------------
__global__ void conv_fp16(const float4* __restrict__ src, __half2* __restrict__ dst, int n4)
{
    int i = blockIdx.x * blockDim.x + threadIdx.x;
    if (i < n4) {
        float4 v = src[i];
        dst[2*i]   = __floats2half2_rn(v.x, v.y);
        dst[2*i+1] = __floats2half2_rn(v.z, v.w);
    }
}
__global__ void conv_w3(const float4* __restrict__ Wq, const float4* __restrict__ Wk,
                        const float4* __restrict__ Wv, int n4)
{
    int i = blockIdx.x * blockDim.x + threadIdx.x;
    const float4* src = (blockIdx.z == 0) ? Wq : (blockIdx.z == 1 ? Wk : Wv);
    __half2* dst = (__half2*)(g_W16 + (size_t)blockIdx.z * Dd * Dd);
    if (i < n4) {
        float4 v = src[i];
        dst[2*i]   = __floats2half2_rn(v.x, v.y);
        dst[2*i+1] = __floats2half2_rn(v.z, v.w);
    }
}

// ---------------------------------------------------------------------------
// Projection GEMM, fp16 HMMA (unchanged from R14): 256 thr, 8 warps, m32n64,
// tile 128x128, K-step 64, 3-stage cp.async, 1 barrier/K-step.
// grid.z==3 slice: mask fp32->fp16 conversion (co-resident, off critical path).
// Q output pre-scaled by log2(e)/8.
// ---------------------------------------------------------------------------
#define PA_ROWB 144
#define PB_ROWB 272
#define PA_STAGE 18432
#define PB_STAGE 17408
#define NSTG 3
#define PROJ_SMEM (NSTG*(PA_STAGE + PB_STAGE))   // 107520
#define N4_M (Bb*Ss*Ss/4)                        // 2097152 float4s

__global__ __launch_bounds__(256, 1) void proj16_kernel(const float4* __restrict__ mask)
{
    // ---- grid.z == 3: mask conversion slice (512 blocks x 4096 float4) ----
    if (blockIdx.z == 3) {
        const int bid = blockIdx.y * gridDim.x + blockIdx.x;   // 0..511
        __half2* d = (__half2*)g_M16;
        const int base = bid * 4096;
        #pragma unroll
        for (int i = 0; i < 16; i++) {
            int j = base + i * 256 + threadIdx.x;
            float4 v = mask[j];
            d[2*j]   = __floats2half2_rn(v.x, v.y);
            d[2*j+1] = __floats2half2_rn(v.z, v.w);
        }
        return;
    }

    extern __shared__ char sm[];
    const uint32_t sb = smem_u32(sm);
    const uint32_t Ab = sb, Bb_ = sb + NSTG*PA_STAGE;

    const int tid = threadIdx.x, wid = tid >> 5, lane = tid & 31;
    const int g = lane >> 2, tig = lane & 3;
    const int wm = wid & 3, wn = wid >> 2;

    const int z  = blockIdx.z;
    const int n0 = blockIdx.x * 128;
    const int m0 = blockIdx.y * 128;
    const __half* Xp = g_X16 + (size_t)m0 * Dd;
    const __half* Wp = g_W16 + (size_t)z * Dd * Dd + n0;
    __half* Out = (z == 0) ? g_Q16 : (z == 1 ? g_K16 : g_V16);
    const float osc = (z == 0) ? 0.18033688f : 1.0f;   // log2(e)/8 folded into Q

    float C[2][8][4];
    #pragma unroll
    for (int mf = 0; mf < 2; mf++)
        #pragma unroll
        for (int nf = 0; nf < 8; nf++)
            #pragma unroll
            for (int r = 0; r < 4; r++) C[mf][nf][r] = 0.f;

    auto stage = [&](int kt, int buf) {
        const int k0 = kt * 64;
        #pragma unroll
        for (int i = 0; i < 4; i++) {
            int ci = tid + 256 * i;
            int row = ci >> 3, seg = ci & 7;
            CP_ASYNC(Ab + buf * PA_STAGE + row * PA_ROWB + seg * 16,
                     Xp + (size_t)row * Dd + k0 + seg * 8);
        }
        #pragma unroll
        for (int i = 0; i < 4; i++) {
            int ci = tid + 256 * i;
            int row = ci >> 4, seg = ci & 15;
            CP_ASYNC(Bb_ + buf * PB_STAGE + row * PB_ROWB + seg * 16,
                     Wp + (size_t)(k0 + row) * Dd + seg * 8);
        }
        CP_COMMIT();
    };

    stage(0, 0);
    stage(1, 1);
    for (int kt = 0; kt < 16; kt++) {
        if (kt == 15) { CP_WAIT(0); }
        else          { CP_WAIT(1); }
        __syncthreads();
        if (kt + 2 < 16) stage(kt + 2, (kt + 2) % NSTG);

        const int buf = kt % NSTG;
        const uint32_t ab = Ab + buf * PA_STAGE;
        const uint32_t bbuf = Bb_ + buf * PB_STAGE;

        uint32_t a[2][4], an[2][4], r[4], rn[4];
        ldsm_x4(a[0], ldsm_addr(ab, wm * 32,      0, PA_ROWB, lane));
        ldsm_x4(a[1], ldsm_addr(ab, wm * 32 + 16, 0, PA_ROWB, lane));
        ldsm_x4_t(r, ldsm_addr(bbuf, 0, (wn * 64) * 2, PB_ROWB, lane));

        #pragma unroll
        for (int k16 = 0; k16 < 4; k16++) {
            #pragma unroll
            for (int nfp = 0; nfp < 4; nfp++) {
                if (nfp < 3) {
                    ldsm_x4_t(rn, ldsm_addr(bbuf, k16 * 16,
                                            (wn * 64 + (nfp + 1) * 16) * 2, PB_ROWB, lane));
                } else if (k16 < 3) {
                    ldsm_x4_t(rn, ldsm_addr(bbuf, (k16 + 1) * 16,
                                            (wn * 64) * 2, PB_ROWB, lane));
                    ldsm_x4(an[0], ldsm_addr(ab, wm * 32,      (k16 + 1) * 32, PA_ROWB, lane));
                    ldsm_x4(an[1], ldsm_addr(ab, wm * 32 + 16, (k16 + 1) * 32, PA_ROWB, lane));
                }
                mma16(C[0][2*nfp],     a[0], r[0], r[1]);
                mma16(C[0][2*nfp + 1], a[0], r[2], r[3]);
                mma16(C[1][2*nfp],     a[1], r[0], r[1]);
                mma16(C[1][2*nfp + 1], a[1], r[2], r[3]);
                #pragma unroll
                for (int q = 0; q < 4; q++) r[q] = rn[q];
            }
            #pragma unroll
            for (int q = 0; q < 4; q++) { a[0][q] = an[0][q]; a[1][q] = an[1][q]; }
        }
    }

    const int h = (n0 >> 6) + wn;
    #pragma unroll
    for (int mf = 0; mf < 2; mf++) {
        int m = m0 + wm * 32 + mf * 16 + g;
        int bidx = m >> 10, s = m & 1023;
        __half* base  = Out + ((size_t)(bidx * Hh + h) * Ss + s) * HDd;
        __half* base2 = base + 8 * HDd;
        #pragma unroll
        for (int nf = 0; nf < 8; nf++) {
            int d = nf * 8 + 2 * tig;
            *(__half2*)(base + d)  = __floats2half2_rn(C[mf][nf][0]*osc, C[mf][nf][1]*osc);
            *(__half2*)(base2 + d) = __floats2half2_rn(C[mf][nf][2]*osc, C[mf][nf][3]*osc);
        }
    }
}

// ---------------------------------------------------------------------------
// Attention, fp16 HMMA: 128 thr (4 warps), m32 per warp -> K/V ldsm traffic
// halves vs m16x8warps (fragments reused across 2 m-frags). Per-16-col chunk
// S -> softmax -> PV keeps live regs ~145 (cap 170 at occ 3). 64-row KV
// double-buffer (smem 55296 -> occupancy 3).
// ---------------------------------------------------------------------------
#define A_ROWB 144                  // 72 halves
#define AQ_BYTES (128*A_ROWB)       // 18432
#define AKV_BYTES (64*A_ROWB)       // 9216
#define ATTN_SMEM (AQ_BYTES + 4*AKV_BYTES)   // 55296

__global__ __launch_bounds__(128, 3) void attn16_kernel(float* __restrict__ out)
{
    extern __shared__ char sm[];
    const uint32_t sb = smem_u32(sm);
    const uint32_t Qb = sb, Kb = sb + AQ_BYTES, Vb = Kb + 2*AKV_BYTES;

    const int tid = threadIdx.x, w = tid >> 5, lane = tid & 31;
    const int g = lane >> 2, tig = lane & 3;
    const int bh = blockIdx.y, b = bh >> 4, h = bh & 15;
    const int q0 = blockIdx.x * 128;
    const int i0 = w * 32;

    const __half* Qg = g_Q16 + (size_t)bh * Ss * HDd + (size_t)q0 * HDd;
    const __half* Kg = g_K16 + (size_t)bh * Ss * HDd;
    const __half* Vg = g_V16 + (size_t)bh * Ss * HDd;
    const __half* mbase = g_M16 + ((size_t)b * Ss + q0 + i0) * Ss;

    auto stageKV = [&](int t0, int buf) {
        #pragma unroll
        for (int i = 0; i < 4; i++) {          // K: 512 chunks / 128 thr
            int ci = tid + 128 * i;
            int row = ci >> 3, seg = ci & 7;
            CP_ASYNC(Kb + buf * AKV_BYTES + row * A_ROWB + seg * 16,
                     Kg + (size_t)(t0 + row) * HDd + seg * 8);
        }
        #pragma unroll
        for (int i = 0; i < 4; i++) {          // V
            int ci = tid + 128 * i;
            int row = ci >> 3, seg = ci & 7;
            CP_ASYNC(Vb + buf * AKV_BYTES + row * A_ROWB + seg * 16,
                     Vg + (size_t)(t0 + row) * HDd + seg * 8);
        }
        CP_COMMIT();
    };

    // prologue: Q (1024 chunks / 128 thr) + KV tile 0 -> one group
    #pragma unroll
    for (int i = 0; i < 8; i++) {
        int ci = tid + 128 * i;
        int row = ci >> 3, seg = ci & 7;
        CP_ASYNC(Qb + row * A_ROWB + seg * 16, Qg + (size_t)row * HDd + seg * 8);
    }
    stageKV(0, 0);
    CP_WAIT(0);
    __syncthreads();

    uint32_t qf[2][4][4];
    #pragma unroll
    for (int mf = 0; mf < 2; mf++)
        #pragma unroll
        for (int k16 = 0; k16 < 4; k16++)
            ldsm_x4(qf[mf][k16], ldsm_addr(Qb, i0 + mf * 16, k16 * 32, A_ROWB, lane));

    float O[2][8][4];
    #pragma unroll
    for (int mf = 0; mf < 2; mf++)
        #pragma unroll
        for (int nf = 0; nf < 8; nf++)
            #pragma unroll
            for (int r = 0; r < 4; r++) O[mf][nf][r] = 0.f;
    float rs[2][2] = {{0.f, 0.f}, {0.f, 0.f}};

    for (int t = 0; t < 16; t++) {
        const int t0 = t * 64, buf = t & 1;
        if (t < 15) { stageKV(t0 + 64, buf ^ 1); CP_WAIT(1); }
        else        { CP_WAIT(0); }
        __syncthreads();

        const uint32_t kb = Kb + buf * AKV_BYTES;
        const uint32_t vb = Vb + buf * AKV_BYTES;

        // per 16-column chunk: S -> softmax -> PV (keeps S live range short)
        #pragma unroll
        for (int c = 0; c < 4; c++) {
            // S chunk: 32 q-rows x 16 t-cols
            float S[2][2][4];
            #pragma unroll
            for (int mf = 0; mf < 2; mf++)
                #pragma unroll
                for (int n2 = 0; n2 < 2; n2++)
                    #pragma unroll
                    for (int r = 0; r < 4; r++) S[mf][n2][r] = 0.f;
            #pragma unroll
            for (int k16 = 0; k16 < 4; k16++) {
                uint32_t kr[4];
                ldsm_x4(kr, ldsm_addr(kb, c * 16, k16 * 32, A_ROWB, lane));
                #pragma unroll
                for (int mf = 0; mf < 2; mf++) {
                    mma16(S[mf][0], qf[mf][k16], kr[0], kr[2]);
                    mma16(S[mf][1], qf[mf][k16], kr[1], kr[3]);
                }
            }

            // P = ex2(S) * mask (fp16 mask), packed fp16; rowsum fp32
            uint32_t Pp[2][2][2];
            #pragma unroll
            for (int mf = 0; mf < 2; mf++) {
                #pragma unroll
                for (int n2 = 0; n2 < 2; n2++) {
                    const __half* mp = mbase + (size_t)(mf * 16 + g) * Ss
                                       + t0 + (c * 2 + n2) * 8 + 2 * tig;
                    float2 m01 = __half22float2(*(const __half2*)mp);
                    float2 m23 = __half22float2(*(const __half2*)(mp + 8 * Ss));
                    float e0 = ex2f(S[mf][n2][0]) * m01.x;
                    float e1 = ex2f(S[mf][n2][1]) * m01.y;
                    float e2 = ex2f(S[mf][n2][2]) * m23.x;
                    float e3 = ex2f(S[mf][n2][3]) * m23.y;
                    rs[mf][0] += e0 + e1;
                    rs[mf][1] += e2 + e3;
                    Pp[mf][n2][0] = h2u(__floats2half2_rn(e0, e1));
                    Pp[mf][n2][1] = h2u(__floats2half2_rn(e2, e3));
                }
            }

            // O += P(chunk) V(rows c*16..c*16+15)
            #pragma unroll
            for (int nfv = 0; nfv < 4; nfv++) {
                uint32_t vr[4];
                ldsm_x4_t(vr, ldsm_addr(vb, c * 16, nfv * 32, A_ROWB, lane));
                #pragma unroll
                for (int mf = 0; mf < 2; mf++) {
                    uint32_t a[4] = { Pp[mf][0][0], Pp[mf][0][1],
                                      Pp[mf][1][0], Pp[mf][1][1] };
                    mma16(O[mf][2*nfv],     a, vr[0], vr[1]);
                    mma16(O[mf][2*nfv + 1], a, vr[2], vr[3]);
                }
            }
        }
        __syncthreads();
    }

    // normalize + store
    #pragma unroll
    for (int mf = 0; mf < 2; mf++) {
        float r0 = rs[mf][0], r1 = rs[mf][1];
        r0 += __shfl_xor_sync(0xffffffffu, r0, 1);
        r0 += __shfl_xor_sync(0xffffffffu, r0, 2);
        r1 += __shfl_xor_sync(0xffffffffu, r1, 1);
        r1 += __shfl_xor_sync(0xffffffffu, r1, 2);
        const float inv0 = 1.0f / (r0 + 1e-8f);
        const float inv1 = 1.0f / (r1 + 1e-8f);
        float* o0 = out + ((size_t)b * Ss + q0 + i0 + mf * 16 + g) * Dd + h * HDd;
        float* o1 = o0 + 8 * Dd;
        #pragma unroll
        for (int nf = 0; nf < 8; nf++) {
            int d = nf * 8 + 2 * tig;
            *(float2*)(o0 + d) = make_float2(O[mf][nf][0] * inv0, O[mf][nf][1] * inv0);
            *(float2*)(o1 + d) = make_float2(O[mf][nf][2] * inv1, O[mf][nf][3] * inv1);
        }
    }
}

// ---------------------------------------------------------------------------
extern "C" void kernel_launch(void* const* d_in, const int* in_sizes, int n_in,
                              void* d_out, int out_size)
{
    const float* x    = (const float*)d_in[0];
    const float* mask = (const float*)d_in[1];
    const float* Wq   = (const float*)d_in[2];
    const float* Wk   = (const float*)d_in[3];
    const float* Wv   = (const float*)d_in[4];
    float* out = (float*)d_out;

    __half* gX; cudaGetSymbolAddress((void**)&gX, g_X16);

    // 1) fp32 -> fp16 pre-pass (x and weights; mask converts inside proj launch)
    const int n4x = Mtot * Dd / 4;
    const int n4w = Dd * Dd / 4;
    conv_fp16<<<(n4x + 255) / 256, 256>>>((const float4*)x, (__half2*)gX, n4x);
    {
        dim3 wgrid((n4w + 255) / 256, 1, 3);
        conv_w3<<<wgrid, 256>>>((const float4*)Wq, (const float4*)Wk,
                                (const float4*)Wv, n4w);
    }

    // 2) projections (fp16 HMMA) + mask conversion as co-resident grid.z=3 slice
    cudaFuncSetAttribute(proj16_kernel, cudaFuncAttributeMaxDynamicSharedMemorySize,
                         PROJ_SMEM);
    dim3 pgrid(Dd / 128, Mtot / 128, 4);
    proj16_kernel<<<pgrid, 256, PROJ_SMEM>>>((const float4*)mask);

    // 3) attention (fp16 HMMA, 4 warps m32, occ 3)
    cudaFuncSetAttribute(attn16_kernel, cudaFuncAttributeMaxDynamicSharedMemorySize,
                         ATTN_SMEM);
    dim3 agrid(Ss / 128, BHh);              // (8, 128)
    attn16_kernel<<<agrid, 128, ATTN_SMEM>>>(out);
}

// round 16
// speedup vs baseline: 1.1330x; 1.0371x over previous
#include <cuda_runtime.h>
#include <cuda_fp16.h>
#include <cstdint>

// Problem constants
#define Hh   16
#define Ss   1024
#define Dd   1024
#define HDd  64
#define Bb   8
#define BHh  (Bb*Hh)      // 128
#define Mtot (Bb*Ss)      // 8192

// fp16 scratch (device globals; no allocation allowed)
__device__ __half g_X16[(size_t)Mtot*Dd];
__device__ __half g_W16[(size_t)3*Dd*Dd];
__device__ __half g_M16[(size_t)Bb*Ss*Ss];         // fp16 mask (0/1 exact)
__device__ __half g_Q16[(size_t)BHh*Ss*HDd];       // head-major, pre-scaled by log2e/8
__device__ __half g_K16[(size_t)BHh*Ss*HDd];
__device__ __half g_V16[(size_t)BHh*Ss*HDd];

// ---------------------------------------------------------------------------
__device__ __forceinline__ uint32_t h2u(__half2 h) {
    union { __half2 h; uint32_t u; } c; c.h = h; return c.u;
}
__device__ __forceinline__ __half2 u2h(uint32_t u) {
    union { __half2 h; uint32_t u; } c; c.u = u; return c.h;
}
// packed fp16x2 exp2 on MUFU (halves the MUFU op count vs scalar f32 ex2)
__device__ __forceinline__ uint32_t ex2_h2(uint32_t s) {
    uint32_t y;
    asm("ex2.approx.f16x2 %0, %1;" : "=r"(y) : "r"(s));
    return y;
}
__device__ __forceinline__ uint32_t smem_u32(const void* p) {
    uint32_t a;
    asm("{ .reg .u64 t; cvta.to.shared.u64 t, %1; cvt.u32.u64 %0, t; }" : "=r"(a) : "l"(p));
    return a;
}
#define CP_ASYNC(dst, src) \
    asm volatile("cp.async.ca.shared.global [%0], [%1], 16;" :: "r"(dst), "l"(src) : "memory")
#define CP_COMMIT() asm volatile("cp.async.commit_group;" ::: "memory")
#define CP_WAIT(n)  asm volatile("cp.async.wait_group %0;" :: "n"(n) : "memory")

__device__ __forceinline__ void ldsm_x4(uint32_t* r, uint32_t addr) {
    asm volatile("ldmatrix.sync.aligned.m8n8.x4.shared.b16 {%0,%1,%2,%3}, [%4];"
                 : "=r"(r[0]), "=r"(r[1]), "=r"(r[2]), "=r"(r[3]) : "r"(addr));
}
__device__ __forceinline__ void ldsm_x4_t(uint32_t* r, uint32_t addr) {
    asm volatile("ldmatrix.sync.aligned.m8n8.x4.trans.shared.b16 {%0,%1,%2,%3}, [%4];"
                 : "=r"(r[0]), "=r"(r[1]), "=r"(r[2]), "=r"(r[3]) : "r"(addr));
}
// fp16 m16n8k16 mma, fp32 accum in-place
__device__ __forceinline__ void mma16(float* c, const uint32_t* a, uint32_t b0, uint32_t b1) {
    asm volatile(
        "mma.sync.aligned.m16n8k16.row.col.f32.f16.f16.f32 "
        "{%0,%1,%2,%3}, {%4,%5,%6,%7}, {%8,%9}, {%0,%1,%2,%3};"
        : "+f"(c[0]), "+f"(c[1]), "+f"(c[2]), "+f"(c[3])
        : "r"(a[0]), "r"(a[1]), "r"(a[2]), "r"(a[3]), "r"(b0), "r"(b1));
}
__device__ __forceinline__ uint32_t ldsm_addr(uint32_t base, int r0, int c0b,
                                              int rowb, int lane) {
    return base + (uint32_t)(r0 + (lane & 15)) * rowb + c0b + ((lane >> 4) << 4);
}

// ---------------------------------------------------------------------------
// fp32 -> fp16 convert pre-passes (x and weights only; mask rides inside proj)
// ---------------------------------------------------------------------------
__global__ void conv_fp16(const float4* __restrict__ src, __half2* __restrict__ dst, int n4)
{
    int i = blockIdx.x * blockDim.x + threadIdx.x;
    if (i < n4) {
        float4 v = src[i];
        dst[2*i]   = __floats2half2_rn(v.x, v.y);
        dst[2*i+1] = __floats2half2_rn(v.z, v.w);
    }
}
__global__ void conv_w3(const float4* __restrict__ Wq, const float4* __restrict__ Wk,
                        const float4* __restrict__ Wv, int n4)
{
    int i = blockIdx.x * blockDim.x + threadIdx.x;
    const float4* src = (blockIdx.z == 0) ? Wq : (blockIdx.z == 1 ? Wk : Wv);
    __half2* dst = (__half2*)(g_W16 + (size_t)blockIdx.z * Dd * Dd);
    if (i < n4) {
        float4 v = src[i];
        dst[2*i]   = __floats2half2_rn(v.x, v.y);
        dst[2*i+1] = __floats2half2_rn(v.z, v.w);
    }
}

// ---------------------------------------------------------------------------
// Projection GEMM, fp16 HMMA (unchanged from R15): 256 thr, 8 warps, m32n64,
// tile 128x128, K-step 64, 3-stage cp.async, 1 barrier/K-step.
// grid.z==3 slice: mask fp32->fp16 conversion (co-resident, off critical path).
// Q output pre-scaled by log2(e)/8.
// ---------------------------------------------------------------------------
#define PA_ROWB 144
#define PB_ROWB 272
#define PA_STAGE 18432
#define PB_STAGE 17408
#define NSTG 3
#define PROJ_SMEM (NSTG*(PA_STAGE + PB_STAGE))   // 107520
#define N4_M (Bb*Ss*Ss/4)                        // 2097152 float4s

__global__ __launch_bounds__(256, 1) void proj16_kernel(const float4* __restrict__ mask)
{
    // ---- grid.z == 3: mask conversion slice (512 blocks x 4096 float4) ----
    if (blockIdx.z == 3) {
        const int bid = blockIdx.y * gridDim.x + blockIdx.x;   // 0..511
        __half2* d = (__half2*)g_M16;
        const int base = bid * 4096;
        #pragma unroll
        for (int i = 0; i < 16; i++) {
            int j = base + i * 256 + threadIdx.x;
            float4 v = mask[j];
            d[2*j]   = __floats2half2_rn(v.x, v.y);
            d[2*j+1] = __floats2half2_rn(v.z, v.w);
        }
        return;
    }

    extern __shared__ char sm[];
    const uint32_t sb = smem_u32(sm);
    const uint32_t Ab = sb, Bb_ = sb + NSTG*PA_STAGE;

    const int tid = threadIdx.x, wid = tid >> 5, lane = tid & 31;
    const int g = lane >> 2, tig = lane & 3;
    const int wm = wid & 3, wn = wid >> 2;

    const int z  = blockIdx.z;
    const int n0 = blockIdx.x * 128;
    const int m0 = blockIdx.y * 128;
    const __half* Xp = g_X16 + (size_t)m0 * Dd;
    const __half* Wp = g_W16 + (size_t)z * Dd * Dd + n0;
    __half* Out = (z == 0) ? g_Q16 : (z == 1 ? g_K16 : g_V16);
    const float osc = (z == 0) ? 0.18033688f : 1.0f;   // log2(e)/8 folded into Q

    float C[2][8][4];
    #pragma unroll
    for (int mf = 0; mf < 2; mf++)
        #pragma unroll
        for (int nf = 0; nf < 8; nf++)
            #pragma unroll
            for (int r = 0; r < 4; r++) C[mf][nf][r] = 0.f;

    auto stage = [&](int kt, int buf) {
        const int k0 = kt * 64;
        #pragma unroll
        for (int i = 0; i < 4; i++) {
            int ci = tid + 256 * i;
            int row = ci >> 3, seg = ci & 7;
            CP_ASYNC(Ab + buf * PA_STAGE + row * PA_ROWB + seg * 16,
                     Xp + (size_t)row * Dd + k0 + seg * 8);
        }
        #pragma unroll
        for (int i = 0; i < 4; i++) {
            int ci = tid + 256 * i;
            int row = ci >> 4, seg = ci & 15;
            CP_ASYNC(Bb_ + buf * PB_STAGE + row * PB_ROWB + seg * 16,
                     Wp + (size_t)(k0 + row) * Dd + seg * 8);
        }
        CP_COMMIT();
    };

    stage(0, 0);
    stage(1, 1);
    for (int kt = 0; kt < 16; kt++) {
        if (kt == 15) { CP_WAIT(0); }
        else          { CP_WAIT(1); }
        __syncthreads();
        if (kt + 2 < 16) stage(kt + 2, (kt + 2) % NSTG);

        const int buf = kt % NSTG;
        const uint32_t ab = Ab + buf * PA_STAGE;
        const uint32_t bbuf = Bb_ + buf * PB_STAGE;

        uint32_t a[2][4], an[2][4], r[4], rn[4];
        ldsm_x4(a[0], ldsm_addr(ab, wm * 32,      0, PA_ROWB, lane));
        ldsm_x4(a[1], ldsm_addr(ab, wm * 32 + 16, 0, PA_ROWB, lane));
        ldsm_x4_t(r, ldsm_addr(bbuf, 0, (wn * 64) * 2, PB_ROWB, lane));

        #pragma unroll
        for (int k16 = 0; k16 < 4; k16++) {
            #pragma unroll
            for (int nfp = 0; nfp < 4; nfp++) {
                if (nfp < 3) {
                    ldsm_x4_t(rn, ldsm_addr(bbuf, k16 * 16,
                                            (wn * 64 + (nfp + 1) * 16) * 2, PB_ROWB, lane));
                } else if (k16 < 3) {
                    ldsm_x4_t(rn, ldsm_addr(bbuf, (k16 + 1) * 16,
                                            (wn * 64) * 2, PB_ROWB, lane));
                    ldsm_x4(an[0], ldsm_addr(ab, wm * 32,      (k16 + 1) * 32, PA_ROWB, lane));
                    ldsm_x4(an[1], ldsm_addr(ab, wm * 32 + 16, (k16 + 1) * 32, PA_ROWB, lane));
                }
                mma16(C[0][2*nfp],     a[0], r[0], r[1]);
                mma16(C[0][2*nfp + 1], a[0], r[2], r[3]);
                mma16(C[1][2*nfp],     a[1], r[0], r[1]);
                mma16(C[1][2*nfp + 1], a[1], r[2], r[3]);
                #pragma unroll
                for (int q = 0; q < 4; q++) r[q] = rn[q];
            }
            #pragma unroll
            for (int q = 0; q < 4; q++) { a[0][q] = an[0][q]; a[1][q] = an[1][q]; }
        }
    }

    const int h = (n0 >> 6) + wn;
    #pragma unroll
    for (int mf = 0; mf < 2; mf++) {
        int m = m0 + wm * 32 + mf * 16 + g;
        int bidx = m >> 10, s = m & 1023;
        __half* base  = Out + ((size_t)(bidx * Hh + h) * Ss + s) * HDd;
        __half* base2 = base + 8 * HDd;
        #pragma unroll
        for (int nf = 0; nf < 8; nf++) {
            int d = nf * 8 + 2 * tig;
            *(__half2*)(base + d)  = __floats2half2_rn(C[mf][nf][0]*osc, C[mf][nf][1]*osc);
            *(__half2*)(base2 + d) = __floats2half2_rn(C[mf][nf][2]*osc, C[mf][nf][3]*osc);
        }
    }
}

// ---------------------------------------------------------------------------
// Attention, fp16 HMMA (R15 structure: 4 warps m32, occ 3, 64-row KV stages),
// NEW: packed f16x2 softmax — ex2.approx.f16x2 (MUFU ops halved), HMUL2 mask,
// rowsum in fp32 unpacked from the SAME fp16 P the PV mma consumes.
// ---------------------------------------------------------------------------
#define A_ROWB 144                  // 72 halves
#define AQ_BYTES (128*A_ROWB)       // 18432
#define AKV_BYTES (64*A_ROWB)       // 9216
#define ATTN_SMEM (AQ_BYTES + 4*AKV_BYTES)   // 55296

__global__ __launch_bounds__(128, 3) void attn16_kernel(float* __restrict__ out)
{
    extern __shared__ char sm[];
    const uint32_t sb = smem_u32(sm);
    const uint32_t Qb = sb, Kb = sb + AQ_BYTES, Vb = Kb + 2*AKV_BYTES;

    const int tid = threadIdx.x, w = tid >> 5, lane = tid & 31;
    const int g = lane >> 2, tig = lane & 3;
    const int bh = blockIdx.y, b = bh >> 4, h = bh & 15;
    const int q0 = blockIdx.x * 128;
    const int i0 = w * 32;

    const __half* Qg = g_Q16 + (size_t)bh * Ss * HDd + (size_t)q0 * HDd;
    const __half* Kg = g_K16 + (size_t)bh * Ss * HDd;
    const __half* Vg = g_V16 + (size_t)bh * Ss * HDd;
    const __half* mbase = g_M16 + ((size_t)b * Ss + q0 + i0) * Ss;

    auto stageKV = [&](int t0, int buf) {
        #pragma unroll
        for (int i = 0; i < 4; i++) {          // K: 512 chunks / 128 thr
            int ci = tid + 128 * i;
            int row = ci >> 3, seg = ci & 7;
            CP_ASYNC(Kb + buf * AKV_BYTES + row * A_ROWB + seg * 16,
                     Kg + (size_t)(t0 + row) * HDd + seg * 8);
        }
        #pragma unroll
        for (int i = 0; i < 4; i++) {          // V
            int ci = tid + 128 * i;
            int row = ci >> 3, seg = ci & 7;
            CP_ASYNC(Vb + buf * AKV_BYTES + row * A_ROWB + seg * 16,
                     Vg + (size_t)(t0 + row) * HDd + seg * 8);
        }
        CP_COMMIT();
    };

    // prologue: Q (1024 chunks / 128 thr) + KV tile 0 -> one group
    #pragma unroll
    for (int i = 0; i < 8; i++) {
        int ci = tid + 128 * i;
        int row = ci >> 3, seg = ci & 7;
        CP_ASYNC(Qb + row * A_ROWB + seg * 16, Qg + (size_t)row * HDd + seg * 8);
    }
    stageKV(0, 0);
    CP_WAIT(0);
    __syncthreads();

    uint32_t qf[2][4][4];
    #pragma unroll
    for (int mf = 0; mf < 2; mf++)
        #pragma unroll
        for (int k16 = 0; k16 < 4; k16++)
            ldsm_x4(qf[mf][k16], ldsm_addr(Qb, i0 + mf * 16, k16 * 32, A_ROWB, lane));

    float O[2][8][4];
    #pragma unroll
    for (int mf = 0; mf < 2; mf++)
        #pragma unroll
        for (int nf = 0; nf < 8; nf++)
            #pragma unroll
            for (int r = 0; r < 4; r++) O[mf][nf][r] = 0.f;
    float rs[2][2] = {{0.f, 0.f}, {0.f, 0.f}};

    for (int t = 0; t < 16; t++) {
        const int t0 = t * 64, buf = t & 1;
        if (t < 15) { stageKV(t0 + 64, buf ^ 1); CP_WAIT(1); }
        else        { CP_WAIT(0); }
        __syncthreads();

        const uint32_t kb = Kb + buf * AKV_BYTES;
        const uint32_t vb = Vb + buf * AKV_BYTES;

        // per 16-column chunk: S -> softmax -> PV
        #pragma unroll
        for (int c = 0; c < 4; c++) {
            // S chunk: 32 q-rows x 16 t-cols
            float S[2][2][4];
            #pragma unroll
            for (int mf = 0; mf < 2; mf++)
                #pragma unroll
                for (int n2 = 0; n2 < 2; n2++)
                    #pragma unroll
                    for (int r = 0; r < 4; r++) S[mf][n2][r] = 0.f;
            #pragma unroll
            for (int k16 = 0; k16 < 4; k16++) {
                uint32_t kr[4];
                ldsm_x4(kr, ldsm_addr(kb, c * 16, k16 * 32, A_ROWB, lane));
                #pragma unroll
                for (int mf = 0; mf < 2; mf++) {
                    mma16(S[mf][0], qf[mf][k16], kr[0], kr[2]);
                    mma16(S[mf][1], qf[mf][k16], kr[1], kr[3]);
                }
            }

            // P = ex2.f16x2(S) * mask (HMUL2); rowsum fp32 from the same fp16 P
            uint32_t Pp[2][2][2];
            #pragma unroll
            for (int mf = 0; mf < 2; mf++) {
                #pragma unroll
                for (int n2 = 0; n2 < 2; n2++) {
                    const __half* mp = mbase + (size_t)(mf * 16 + g) * Ss
                                       + t0 + (c * 2 + n2) * 8 + 2 * tig;
                    uint32_t m01 = *(const uint32_t*)mp;
                    uint32_t m23 = *(const uint32_t*)(mp + 8 * Ss);
                    uint32_t s01 = h2u(__floats2half2_rn(S[mf][n2][0], S[mf][n2][1]));
                    uint32_t s23 = h2u(__floats2half2_rn(S[mf][n2][2], S[mf][n2][3]));
                    uint32_t e01 = h2u(__hmul2(u2h(ex2_h2(s01)), u2h(m01)));
                    uint32_t e23 = h2u(__hmul2(u2h(ex2_h2(s23)), u2h(m23)));
                    Pp[mf][n2][0] = e01;
                    Pp[mf][n2][1] = e23;
                    float2 f01 = __half22float2(u2h(e01));
                    float2 f23 = __half22float2(u2h(e23));
                    rs[mf][0] += f01.x + f01.y;
                    rs[mf][1] += f23.x + f23.y;
                }
            }

            // O += P(chunk) V(rows c*16..c*16+15)
            #pragma unroll
            for (int nfv = 0; nfv < 4; nfv++) {
                uint32_t vr[4];
                ldsm_x4_t(vr, ldsm_addr(vb, c * 16, nfv * 32, A_ROWB, lane));
                #pragma unroll
                for (int mf = 0; mf < 2; mf++) {
                    uint32_t a[4] = { Pp[mf][0][0], Pp[mf][0][1],
                                      Pp[mf][1][0], Pp[mf][1][1] };
                    mma16(O[mf][2*nfv],     a, vr[0], vr[1]);
                    mma16(O[mf][2*nfv + 1], a, vr[2], vr[3]);
                }
            }
        }
        __syncthreads();
    }

    // normalize + store
    #pragma unroll
    for (int mf = 0; mf < 2; mf++) {
        float r0 = rs[mf][0], r1 = rs[mf][1];
        r0 += __shfl_xor_sync(0xffffffffu, r0, 1);
        r0 += __shfl_xor_sync(0xffffffffu, r0, 2);
        r1 += __shfl_xor_sync(0xffffffffu, r1, 1);
        r1 += __shfl_xor_sync(0xffffffffu, r1, 2);
        const float inv0 = 1.0f / (r0 + 1e-8f);
        const float inv1 = 1.0f / (r1 + 1e-8f);
        float* o0 = out + ((size_t)b * Ss + q0 + i0 + mf * 16 + g) * Dd + h * HDd;
        float* o1 = o0 + 8 * Dd;
        #pragma unroll
        for (int nf = 0; nf < 8; nf++) {
            int d = nf * 8 + 2 * tig;
            *(float2*)(o0 + d) = make_float2(O[mf][nf][0] * inv0, O[mf][nf][1] * inv0);
            *(float2*)(o1 + d) = make_float2(O[mf][nf][2] * inv1, O[mf][nf][3] * inv1);
        }
    }
}

// ---------------------------------------------------------------------------
extern "C" void kernel_launch(void* const* d_in, const int* in_sizes, int n_in,
                              void* d_out, int out_size)
{
    const float* x    = (const float*)d_in[0];
    const float* mask = (const float*)d_in[1];
    const float* Wq   = (const float*)d_in[2];
    const float* Wk   = (const float*)d_in[3];
    const float* Wv   = (const float*)d_in[4];
    float* out = (float*)d_out;

    __half* gX; cudaGetSymbolAddress((void**)&gX, g_X16);

    // 1) fp32 -> fp16 pre-pass (x and weights; mask converts inside proj launch)
    const int n4x = Mtot * Dd / 4;
    const int n4w = Dd * Dd / 4;
    conv_fp16<<<(n4x + 255) / 256, 256>>>((const float4*)x, (__half2*)gX, n4x);
    {
        dim3 wgrid((n4w + 255) / 256, 1, 3);
        conv_w3<<<wgrid, 256>>>((const float4*)Wq, (const float4*)Wk,
                                (const float4*)Wv, n4w);
    }

    // 2) projections (fp16 HMMA) + mask conversion as co-resident grid.z=3 slice
    cudaFuncSetAttribute(proj16_kernel, cudaFuncAttributeMaxDynamicSharedMemorySize,
                         PROJ_SMEM);
    dim3 pgrid(Dd / 128, Mtot / 128, 4);
    proj16_kernel<<<pgrid, 256, PROJ_SMEM>>>((const float4*)mask);

    // 3) attention (fp16 HMMA, 4 warps m32, f16x2 softmax)
    cudaFuncSetAttribute(attn16_kernel, cudaFuncAttributeMaxDynamicSharedMemorySize,
                         ATTN_SMEM);
    dim3 agrid(Ss / 128, BHh);              // (8, 128)
    attn16_kernel<<<agrid, 128, ATTN_SMEM>>>(out);
}

// round 17
// speedup vs baseline: 1.1686x; 1.0314x over previous
#include <cuda_runtime.h>
#include <cuda_fp16.h>
#include <cstdint>

// Problem constants
#define Hh   16
#define Ss   1024
#define Dd   1024
#define HDd  64
#define Bb   8
#define BHh  (Bb*Hh)      // 128
#define Mtot (Bb*Ss)      // 8192

// fp16 scratch (device globals; no allocation allowed)
__device__ __half g_X16[(size_t)Mtot*Dd];
__device__ __half g_W16[(size_t)3*Dd*Dd];
// fragment-permuted fp16 mask: uint4 entries [b][tile16][r16(64)][chunk4][lane32]
// entry = {rowg/n2=0, rowg/n2=1, rowg8/n2=0, rowg8/n2=1} half2 pairs
__device__ __half g_M16[(size_t)Bb*Ss*Ss];
__device__ __half g_Q16[(size_t)BHh*Ss*HDd];       // head-major, pre-scaled by log2e/8
__device__ __half g_K16[(size_t)BHh*Ss*HDd];
__device__ __half g_V16[(size_t)BHh*Ss*HDd];

// ---------------------------------------------------------------------------
__device__ __forceinline__ uint32_t h2u(__half2 h) {
    union { __half2 h; uint32_t u; } c; c.h = h; return c.u;
}
__device__ __forceinline__ __half2 u2h(uint32_t u) {
    union { __half2 h; uint32_t u; } c; c.u = u; return c.h;
}
__device__ __forceinline__ uint32_t ex2_h2(uint32_t s) {
    uint32_t y;
    asm("ex2.approx.f16x2 %0, %1;" : "=r"(y) : "r"(s));
    return y;
}
__device__ __forceinline__ uint32_t smem_u32(const void* p) {
    uint32_t a;
    asm("{ .reg .u64 t; cvta.to.shared.u64 t, %1; cvt.u32.u64 %0, t; }" : "=r"(a) : "l"(p));
    return a;
}
#define CP_ASYNC(dst, src) \
    asm volatile("cp.async.ca.shared.global [%0], [%1], 16;" :: "r"(dst), "l"(src) : "memory")
#define CP_COMMIT() asm volatile("cp.async.commit_group;" ::: "memory")
#define CP_WAIT(n)  asm volatile("cp.async.wait_group %0;" :: "n"(n) : "memory")

__device__ __forceinline__ void ldsm_x4(uint32_t* r, uint32_t addr) {
    asm volatile("ldmatrix.sync.aligned.m8n8.x4.shared.b16 {%0,%1,%2,%3}, [%4];"
                 : "=r"(r[0]), "=r"(r[1]), "=r"(r[2]), "=r"(r[3]) : "r"(addr));
}
__device__ __forceinline__ void ldsm_x4_t(uint32_t* r, uint32_t addr) {
    asm volatile("ldmatrix.sync.aligned.m8n8.x4.trans.shared.b16 {%0,%1,%2,%3}, [%4];"
                 : "=r"(r[0]), "=r"(r[1]), "=r"(r[2]), "=r"(r[3]) : "r"(addr));
}
// fp16 m16n8k16 mma, fp32 accum in-place
__device__ __forceinline__ void mma16(float* c, const uint32_t* a, uint32_t b0, uint32_t b1) {
    asm volatile(
        "mma.sync.aligned.m16n8k16.row.col.f32.f16.f16.f32 "
        "{%0,%1,%2,%3}, {%4,%5,%6,%7}, {%8,%9}, {%0,%1,%2,%3};"
        : "+f"(c[0]), "+f"(c[1]), "+f"(c[2]), "+f"(c[3])
        : "r"(a[0]), "r"(a[1]), "r"(a[2]), "r"(a[3]), "r"(b0), "r"(b1));
}
__device__ __forceinline__ uint32_t ldsm_addr(uint32_t base, int r0, int c0b,
                                              int rowb, int lane) {
    return base + (uint32_t)(r0 + (lane & 15)) * rowb + c0b + ((lane >> 4) << 4);
}

// ---------------------------------------------------------------------------
// fp32 -> fp16 convert pre-passes (x and weights only; mask rides inside proj)
// ---------------------------------------------------------------------------
__global__ void conv_fp16(const float4* __restrict__ src, __half2* __restrict__ dst, int n4)
{
    int i = blockIdx.x * blockDim.x + threadIdx.x;
    if (i < n4) {
        float4 v = src[i];
        dst[2*i]   = __floats2half2_rn(v.x, v.y);
        dst[2*i+1] = __floats2half2_rn(v.z, v.w);
    }
}
__global__ void conv_w3(const float4* __restrict__ Wq, const float4* __restrict__ Wk,
                        const float4* __restrict__ Wv, int n4)
{
    int i = blockIdx.x * blockDim.x + threadIdx.x;
    const float4* src = (blockIdx.z == 0) ? Wq : (blockIdx.z == 1 ? Wk : Wv);
    __half2* dst = (__half2*)(g_W16 + (size_t)blockIdx.z * Dd * Dd);
    if (i < n4) {
        float4 v = src[i];
        dst[2*i]   = __floats2half2_rn(v.x, v.y);
        dst[2*i+1] = __floats2half2_rn(v.z, v.w);
    }
}

// ---------------------------------------------------------------------------
// Projection GEMM, fp16 HMMA (unchanged compute path). grid.z==3 slice now
// GATHERS the mask into MMA-fragment order (uint4 per (lane,chunk)) so attn's
// mask reads become fully coalesced LDG.128.
// ---------------------------------------------------------------------------
#define PA_ROWB 144
#define PB_ROWB 272
#define PA_STAGE 18432
#define PB_STAGE 17408
#define NSTG 3
#define PROJ_SMEM (NSTG*(PA_STAGE + PB_STAGE))   // 107520

__global__ __launch_bounds__(256, 1) void proj16_kernel(const float* __restrict__ maskf)
{
    // ---- grid.z == 3: mask permute+convert slice ----
    // 1,048,576 uint4 entries; 512 blocks x 256 thr x 8 entries.
    if (blockIdx.z == 3) {
        uint4* pm = (uint4*)g_M16;
        const int bid = blockIdx.y * gridDim.x + blockIdx.x;   // 0..511
        #pragma unroll
        for (int it = 0; it < 8; it++) {
            int e = bid * 2048 + it * 256 + threadIdx.x;
            int lane = e & 31;
            int c    = (e >> 5) & 3;
            int r16  = (e >> 7) & 63;
            int t    = (e >> 13) & 15;
            int b    = e >> 17;
            int g = lane >> 2, tig = lane & 3;
            int row = r16 * 16 + g;
            int col = t * 64 + c * 16 + 2 * tig;
            const float* mr = maskf + ((size_t)b * Ss + row) * Ss + col;
            float2 a0 = *(const float2*)(mr);               // row g,  n2=0
            float2 a1 = *(const float2*)(mr + 8);           // row g,  n2=1
            float2 a2 = *(const float2*)(mr + 8 * Ss);      // row g+8,n2=0
            float2 a3 = *(const float2*)(mr + 8 * Ss + 8);  // row g+8,n2=1
            uint4 o;
            o.x = h2u(__floats2half2_rn(a0.x, a0.y));
            o.y = h2u(__floats2half2_rn(a1.x, a1.y));
            o.z = h2u(__floats2half2_rn(a2.x, a2.y));
            o.w = h2u(__floats2half2_rn(a3.x, a3.y));
            pm[e] = o;
        }
        return;
    }

    extern __shared__ char sm[];
    const uint32_t sb = smem_u32(sm);
    const uint32_t Ab = sb, Bb_ = sb + NSTG*PA_STAGE;

    const int tid = threadIdx.x, wid = tid >> 5, lane = tid & 31;
    const int g = lane >> 2, tig = lane & 3;
    const int wm = wid & 3, wn = wid >> 2;

    const int z  = blockIdx.z;
    const int n0 = blockIdx.x * 128;
    const int m0 = blockIdx.y * 128;
    const __half* Xp = g_X16 + (size_t)m0 * Dd;
    const __half* Wp = g_W16 + (size_t)z * Dd * Dd + n0;
    __half* Out = (z == 0) ? g_Q16 : (z == 1 ? g_K16 : g_V16);
    const float osc = (z == 0) ? 0.18033688f : 1.0f;   // log2(e)/8 folded into Q

    float C[2][8][4];
    #pragma unroll
    for (int mf = 0; mf < 2; mf++)
        #pragma unroll
        for (int nf = 0; nf < 8; nf++)
            #pragma unroll
            for (int r = 0; r < 4; r++) C[mf][nf][r] = 0.f;

    auto stage = [&](int kt, int buf) {
        const int k0 = kt * 64;
        #pragma unroll
        for (int i = 0; i < 4; i++) {
            int ci = tid + 256 * i;
            int row = ci >> 3, seg = ci & 7;
            CP_ASYNC(Ab + buf * PA_STAGE + row * PA_ROWB + seg * 16,
                     Xp + (size_t)row * Dd + k0 + seg * 8);
        }
        #pragma unroll
        for (int i = 0; i < 4; i++) {
            int ci = tid + 256 * i;
            int row = ci >> 4, seg = ci & 15;
            CP_ASYNC(Bb_ + buf * PB_STAGE + row * PB_ROWB + seg * 16,
                     Wp + (size_t)(k0 + row) * Dd + seg * 8);
        }
        CP_COMMIT();
    };

    stage(0, 0);
    stage(1, 1);
    for (int kt = 0; kt < 16; kt++) {
        if (kt == 15) { CP_WAIT(0); }
        else          { CP_WAIT(1); }
        __syncthreads();
        if (kt + 2 < 16) stage(kt + 2, (kt + 2) % NSTG);

        const int buf = kt % NSTG;
        const uint32_t ab = Ab + buf * PA_STAGE;
        const uint32_t bbuf = Bb_ + buf * PB_STAGE;

        uint32_t a[2][4], an[2][4], r[4], rn[4];
        ldsm_x4(a[0], ldsm_addr(ab, wm * 32,      0, PA_ROWB, lane));
        ldsm_x4(a[1], ldsm_addr(ab, wm * 32 + 16, 0, PA_ROWB, lane));
        ldsm_x4_t(r, ldsm_addr(bbuf, 0, (wn * 64) * 2, PB_ROWB, lane));

        #pragma unroll
        for (int k16 = 0; k16 < 4; k16++) {
            #pragma unroll
            for (int nfp = 0; nfp < 4; nfp++) {
                if (nfp < 3) {
                    ldsm_x4_t(rn, ldsm_addr(bbuf, k16 * 16,
                                            (wn * 64 + (nfp + 1) * 16) * 2, PB_ROWB, lane));
                } else if (k16 < 3) {
                    ldsm_x4_t(rn, ldsm_addr(bbuf, (k16 + 1) * 16,
                                            (wn * 64) * 2, PB_ROWB, lane));
                    ldsm_x4(an[0], ldsm_addr(ab, wm * 32,      (k16 + 1) * 32, PA_ROWB, lane));
                    ldsm_x4(an[1], ldsm_addr(ab, wm * 32 + 16, (k16 + 1) * 32, PA_ROWB, lane));
                }
                mma16(C[0][2*nfp],     a[0], r[0], r[1]);
                mma16(C[0][2*nfp + 1], a[0], r[2], r[3]);
                mma16(C[1][2*nfp],     a[1], r[0], r[1]);
                mma16(C[1][2*nfp + 1], a[1], r[2], r[3]);
                #pragma unroll
                for (int q = 0; q < 4; q++) r[q] = rn[q];
            }
            #pragma unroll
            for (int q = 0; q < 4; q++) { a[0][q] = an[0][q]; a[1][q] = an[1][q]; }
        }
    }

    const int h = (n0 >> 6) + wn;
    #pragma unroll
    for (int mf = 0; mf < 2; mf++) {
        int m = m0 + wm * 32 + mf * 16 + g;
        int bidx = m >> 10, s = m & 1023;
        __half* base  = Out + ((size_t)(bidx * Hh + h) * Ss + s) * HDd;
        __half* base2 = base + 8 * HDd;
        #pragma unroll
        for (int nf = 0; nf < 8; nf++) {
            int d = nf * 8 + 2 * tig;
            *(__half2*)(base + d)  = __floats2half2_rn(C[mf][nf][0]*osc, C[mf][nf][1]*osc);
            *(__half2*)(base2 + d) = __floats2half2_rn(C[mf][nf][2]*osc, C[mf][nf][3]*osc);
        }
    }
}

// ---------------------------------------------------------------------------
// Attention, fp16 HMMA (R16 structure: 4 warps m32, occ 3, f16x2 softmax),
// NEW: mask reads via fragment-permuted uint4 (one coalesced LDG.128 per
// (mf, chunk) instead of 4 scattered LDG.32).
// ---------------------------------------------------------------------------
#define A_ROWB 144                  // 72 halves
#define AQ_BYTES (128*A_ROWB)       // 18432
#define AKV_BYTES (64*A_ROWB)       // 9216
#define ATTN_SMEM (AQ_BYTES + 4*AKV_BYTES)   // 55296

__global__ __launch_bounds__(128, 3) void attn16_kernel(float* __restrict__ out)
{
    extern __shared__ char sm[];
    const uint32_t sb = smem_u32(sm);
    const uint32_t Qb = sb, Kb = sb + AQ_BYTES, Vb = Kb + 2*AKV_BYTES;

    const int tid = threadIdx.x, w = tid >> 5, lane = tid & 31;
    const int g = lane >> 2, tig = lane & 3;
    const int bh = blockIdx.y, b = bh >> 4, h = bh & 15;
    const int q0 = blockIdx.x * 128;
    const int i0 = w * 32;

    const __half* Qg = g_Q16 + (size_t)bh * Ss * HDd + (size_t)q0 * HDd;
    const __half* Kg = g_K16 + (size_t)bh * Ss * HDd;
    const __half* Vg = g_V16 + (size_t)bh * Ss * HDd;
    // fragment-permuted mask: entry ((b*16+t)*64 + r16)*128 + c*32 + lane
    const uint4* pmask = (const uint4*)g_M16 + (size_t)b * 131072 + lane;
    const int r16_0 = blockIdx.x * 8 + w * 2;   // r16 for mf=0 (mf=1 -> +1)

    auto stageKV = [&](int t0, int buf) {
        #pragma unroll
        for (int i = 0; i < 4; i++) {          // K: 512 chunks / 128 thr
            int ci = tid + 128 * i;
            int row = ci >> 3, seg = ci & 7;
            CP_ASYNC(Kb + buf * AKV_BYTES + row * A_ROWB + seg * 16,
                     Kg + (size_t)(t0 + row) * HDd + seg * 8);
        }
        #pragma unroll
        for (int i = 0; i < 4; i++) {          // V
            int ci = tid + 128 * i;
            int row = ci >> 3, seg = ci & 7;
            CP_ASYNC(Vb + buf * AKV_BYTES + row * A_ROWB + seg * 16,
                     Vg + (size_t)(t0 + row) * HDd + seg * 8);
        }
        CP_COMMIT();
    };

    // prologue: Q (1024 chunks / 128 thr) + KV tile 0 -> one group
    #pragma unroll
    for (int i = 0; i < 8; i++) {
        int ci = tid + 128 * i;
        int row = ci >> 3, seg = ci & 7;
        CP_ASYNC(Qb + row * A_ROWB + seg * 16, Qg + (size_t)row * HDd + seg * 8);
    }
    stageKV(0, 0);
    CP_WAIT(0);
    __syncthreads();

    uint32_t qf[2][4][4];
    #pragma unroll
    for (int mf = 0; mf < 2; mf++)
        #pragma unroll
        for (int k16 = 0; k16 < 4; k16++)
            ldsm_x4(qf[mf][k16], ldsm_addr(Qb, i0 + mf * 16, k16 * 32, A_ROWB, lane));

    float O[2][8][4];
    #pragma unroll
    for (int mf = 0; mf < 2; mf++)
        #pragma unroll
        for (int nf = 0; nf < 8; nf++)
            #pragma unroll
            for (int r = 0; r < 4; r++) O[mf][nf][r] = 0.f;
    float rs[2][2] = {{0.f, 0.f}, {0.f, 0.f}};

    for (int t = 0; t < 16; t++) {
        const int t0 = t * 64, buf = t & 1;
        if (t < 15) { stageKV(t0 + 64, buf ^ 1); CP_WAIT(1); }
        else        { CP_WAIT(0); }
        __syncthreads();

        const uint32_t kb = Kb + buf * AKV_BYTES;
        const uint32_t vb = Vb + buf * AKV_BYTES;
        const uint4* pmt = pmask + (size_t)(t * 64 + r16_0) * 128;

        // per 16-column chunk: S -> softmax -> PV
        #pragma unroll
        for (int c = 0; c < 4; c++) {
            // S chunk: 32 q-rows x 16 t-cols
            float S[2][2][4];
            #pragma unroll
            for (int mf = 0; mf < 2; mf++)
                #pragma unroll
                for (int n2 = 0; n2 < 2; n2++)
                    #pragma unroll
                    for (int r = 0; r < 4; r++) S[mf][n2][r] = 0.f;
            #pragma unroll
            for (int k16 = 0; k16 < 4; k16++) {
                uint32_t kr[4];
                ldsm_x4(kr, ldsm_addr(kb, c * 16, k16 * 32, A_ROWB, lane));
                #pragma unroll
                for (int mf = 0; mf < 2; mf++) {
                    mma16(S[mf][0], qf[mf][k16], kr[0], kr[2]);
                    mma16(S[mf][1], qf[mf][k16], kr[1], kr[3]);
                }
            }

            // P = ex2.f16x2(S) * mask (coalesced uint4 mask); rowsum fp32
            uint32_t Pp[2][2][2];
            #pragma unroll
            for (int mf = 0; mf < 2; mf++) {
                uint4 mq = pmt[(size_t)mf * 128 + c * 32];
                #pragma unroll
                for (int n2 = 0; n2 < 2; n2++) {
                    uint32_t mg  = n2 ? mq.y : mq.x;   // row g
                    uint32_t mg8 = n2 ? mq.w : mq.z;   // row g+8
                    uint32_t s01 = h2u(__floats2half2_rn(S[mf][n2][0], S[mf][n2][1]));
                    uint32_t s23 = h2u(__floats2half2_rn(S[mf][n2][2], S[mf][n2][3]));
                    uint32_t e01 = h2u(__hmul2(u2h(ex2_h2(s01)), u2h(mg)));
                    uint32_t e23 = h2u(__hmul2(u2h(ex2_h2(s23)), u2h(mg8)));
                    Pp[mf][n2][0] = e01;
                    Pp[mf][n2][1] = e23;
                    float2 f01 = __half22float2(u2h(e01));
                    float2 f23 = __half22float2(u2h(e23));
                    rs[mf][0] += f01.x + f01.y;
                    rs[mf][1] += f23.x + f23.y;
                }
            }

            // O += P(chunk) V(rows c*16..c*16+15)
            #pragma unroll
            for (int nfv = 0; nfv < 4; nfv++) {
                uint32_t vr[4];
                ldsm_x4_t(vr, ldsm_addr(vb, c * 16, nfv * 32, A_ROWB, lane));
                #pragma unroll
                for (int mf = 0; mf < 2; mf++) {
                    uint32_t a[4] = { Pp[mf][0][0], Pp[mf][0][1],
                                      Pp[mf][1][0], Pp[mf][1][1] };
                    mma16(O[mf][2*nfv],     a, vr[0], vr[1]);
                    mma16(O[mf][2*nfv + 1], a, vr[2], vr[3]);
                }
            }
        }
        __syncthreads();
    }

    // normalize + store
    #pragma unroll
    for (int mf = 0; mf < 2; mf++) {
        float r0 = rs[mf][0], r1 = rs[mf][1];
        r0 += __shfl_xor_sync(0xffffffffu, r0, 1);
        r0 += __shfl_xor_sync(0xffffffffu, r0, 2);
        r1 += __shfl_xor_sync(0xffffffffu, r1, 1);
        r1 += __shfl_xor_sync(0xffffffffu, r1, 2);
        const float inv0 = 1.0f / (r0 + 1e-8f);
        const float inv1 = 1.0f / (r1 + 1e-8f);
        float* o0 = out + ((size_t)b * Ss + q0 + i0 + mf * 16 + g) * Dd + h * HDd;
        float* o1 = o0 + 8 * Dd;
        #pragma unroll
        for (int nf = 0; nf < 8; nf++) {
            int d = nf * 8 + 2 * tig;
            *(float2*)(o0 + d) = make_float2(O[mf][nf][0] * inv0, O[mf][nf][1] * inv0);
            *(float2*)(o1 + d) = make_float2(O[mf][nf][2] * inv1, O[mf][nf][3] * inv1);
        }
    }
}

// ---------------------------------------------------------------------------
extern "C" void kernel_launch(void* const* d_in, const int* in_sizes, int n_in,
                              void* d_out, int out_size)
{
    const float* x    = (const float*)d_in[0];
    const float* mask = (const float*)d_in[1];
    const float* Wq   = (const float*)d_in[2];
    const float* Wk   = (const float*)d_in[3];
    const float* Wv   = (const float*)d_in[4];
    float* out = (float*)d_out;

    __half* gX; cudaGetSymbolAddress((void**)&gX, g_X16);

    // 1) fp32 -> fp16 pre-pass (x and weights; mask permutes inside proj launch)
    const int n4x = Mtot * Dd / 4;
    const int n4w = Dd * Dd / 4;
    conv_fp16<<<(n4x + 255) / 256, 256>>>((const float4*)x, (__half2*)gX, n4x);
    {
        dim3 wgrid((n4w + 255) / 256, 1, 3);
        conv_w3<<<wgrid, 256>>>((const float4*)Wq, (const float4*)Wk,
                                (const float4*)Wv, n4w);
    }

    // 2) projections (fp16 HMMA) + mask permute as co-resident grid.z=3 slice
    cudaFuncSetAttribute(proj16_kernel, cudaFuncAttributeMaxDynamicSharedMemorySize,
                         PROJ_SMEM);
    dim3 pgrid(Dd / 128, Mtot / 128, 4);
    proj16_kernel<<<pgrid, 256, PROJ_SMEM>>>(mask);

    // 3) attention (fp16 HMMA, 4 warps m32, f16x2 softmax, coalesced mask)
    cudaFuncSetAttribute(attn16_kernel, cudaFuncAttributeMaxDynamicSharedMemorySize,
                         ATTN_SMEM);
    dim3 agrid(Ss / 128, BHh);              // (8, 128)
    attn16_kernel<<<agrid, 128, ATTN_SMEM>>>(out);
}